// round 3
// baseline (speedup 1.0000x reference)
#include <cuda_runtime.h>
#include <math.h>

#define NN 100000
#define EE 1200000
#define BB 128
#define HH 64
#define GN_EPS 1e-5f
#define SCAN_NBLK ((NN + 1023) / 1024)

// ---------------- device scratch (no allocations allowed) ----------------
__device__ __align__(16) int   g_counts[NN];
__device__ __align__(16) int   g_fill[NN];
__device__ __align__(16) int   g_rowptr[NN];
__device__ __align__(16) int   g_col[EE];
__device__ __align__(16) int   g_blocksum[SCAN_NBLK + 1];
__device__ __align__(16) int   g_blockoff[SCAN_NBLK + 1];
__device__ __align__(16) int   g_gstart[BB + 1];
__device__ __align__(16) float g_bufA[NN * HH];   // agg output, MLP in-place
__device__ __align__(16) float g_hcur[NN * HH];   // current layer output
__device__ __align__(16) float g_hsum[NN * HH];   // residual sum h1+h2+h3
__device__ __align__(16) float g_ssum[BB * HH];
__device__ __align__(16) float g_ssq[BB * HH];
__device__ __align__(16) float g_scale[BB * HH];
__device__ __align__(16) float g_shift[BB * HH];
__device__ __align__(16) float g_gate[NN];
__device__ __align__(16) float g_att[BB * HH];
__device__ __align__(16) float g_meanp[BB * HH];
__device__ __align__(16) float g_maxp[BB * HH];

// ---------------- CSR build ----------------
__global__ void k_zero() {
    int i = blockIdx.x * blockDim.x + threadIdx.x;
    if (i < NN) { g_counts[i] = 0; g_fill[i] = 0; }
}

__global__ void k_hist(const int* __restrict__ ei) {
    int e = blockIdx.x * blockDim.x + threadIdx.x;
    if (e < EE) atomicAdd(&g_counts[ei[EE + e]], 1);
}

__global__ void k_scan1() {
    __shared__ int s[1024];
    int tid = threadIdx.x;
    int i = blockIdx.x * 1024 + tid;
    int v = (i < NN) ? g_counts[i] : 0;
    s[tid] = v;
    __syncthreads();
    for (int off = 1; off < 1024; off <<= 1) {
        int t = (tid >= off) ? s[tid - off] : 0;
        __syncthreads();
        s[tid] += t;
        __syncthreads();
    }
    if (i < NN) g_rowptr[i] = s[tid] - v;      // exclusive
    if (tid == 1023) g_blocksum[blockIdx.x] = s[1023];
}

__global__ void k_scan2() {
    if (threadIdx.x == 0) {
        int acc = 0;
        for (int k = 0; k < SCAN_NBLK; k++) { g_blockoff[k] = acc; acc += g_blocksum[k]; }
    }
}

__global__ void k_scan3() {
    int i = blockIdx.x * blockDim.x + threadIdx.x;
    if (i < NN) g_rowptr[i] += g_blockoff[i >> 10];
}

__global__ void k_fill(const int* __restrict__ ei) {
    int e = blockIdx.x * blockDim.x + threadIdx.x;
    if (e < EE) {
        int dst = ei[EE + e];
        int pos = g_rowptr[dst] + atomicAdd(&g_fill[dst], 1);
        g_col[pos] = ei[e];
    }
}

__global__ void k_gstart(const int* __restrict__ batch) {
    int b = threadIdx.x;
    if (b > BB) return;
    if (b == BB) { g_gstart[BB] = NN; return; }
    int lo = 0, hi = NN;
    while (lo < hi) {
        int mid = (lo + hi) >> 1;
        if (batch[mid] < b) lo = mid + 1; else hi = mid;
    }
    g_gstart[b] = lo;
}

// ---------------- GIN aggregation: bufA = in + sum_{j->i} in_j ----------------
__global__ void k_agg(const float* __restrict__ xin, int use_x) {
    int gw = (blockIdx.x * blockDim.x + threadIdx.x) >> 5;
    int lane = threadIdx.x & 31;
    if (gw >= NN) return;
    const float* __restrict__ in = use_x ? xin : (const float*)g_hcur;
    int node = gw;
    float acc0 = in[node * HH + lane];
    float acc1 = in[node * HH + 32 + lane];
    int rs = g_rowptr[node];
    int re = rs + g_counts[node];
    for (int e = rs; e < re; e++) {
        int s = g_col[e];
        acc0 += in[s * HH + lane];
        acc1 += in[s * HH + 32 + lane];
    }
    g_bufA[node * HH + lane] = acc0;
    g_bufA[node * HH + 32 + lane] = acc1;
}

// ---------------- MLP: buf = relu(buf @ W1 + b1) @ W2 + b2 (in-place) ----------------
__global__ void k_mlp(const float* __restrict__ W1, const float* __restrict__ B1,
                      const float* __restrict__ W2, const float* __restrict__ B2) {
    __shared__ __align__(16) float w1s[HH * HH];
    __shared__ __align__(16) float w2s[HH * HH];
    __shared__ __align__(16) float ts[32 * HH];
    __shared__ float b1s[HH], b2s[HH];
    int tid = threadIdx.x;
    for (int i = tid; i < HH * HH; i += 256) { w1s[i] = W1[i]; w2s[i] = W2[i]; }
    if (tid < HH) { b1s[tid] = B1[tid]; b2s[tid] = B2[tid]; }
    int n0 = blockIdx.x * 32;
    for (int i = tid; i < 32 * HH; i += 256) {
        int node = n0 + (i >> 6);
        ts[i] = (node < NN) ? g_bufA[n0 * HH + i] : 0.f;
    }
    __syncthreads();

    int nn = tid >> 3;            // node within tile (0..31)
    int j0 = (tid & 7) * 8;       // output channel group
    float acc[8];

    // GEMM 1 + ReLU
    #pragma unroll
    for (int j = 0; j < 8; j++) acc[j] = b1s[j0 + j];
    #pragma unroll 8
    for (int k = 0; k < HH; k++) {
        float a = ts[nn * HH + k];
        float4 wa = *(const float4*)&w1s[k * HH + j0];
        float4 wb = *(const float4*)&w1s[k * HH + j0 + 4];
        acc[0] += a * wa.x; acc[1] += a * wa.y; acc[2] += a * wa.z; acc[3] += a * wa.w;
        acc[4] += a * wb.x; acc[5] += a * wb.y; acc[6] += a * wb.z; acc[7] += a * wb.w;
    }
    __syncthreads();
    #pragma unroll
    for (int j = 0; j < 8; j++) ts[nn * HH + j0 + j] = fmaxf(acc[j], 0.f);
    __syncthreads();

    // GEMM 2
    #pragma unroll
    for (int j = 0; j < 8; j++) acc[j] = b2s[j0 + j];
    #pragma unroll 8
    for (int k = 0; k < HH; k++) {
        float a = ts[nn * HH + k];
        float4 wa = *(const float4*)&w2s[k * HH + j0];
        float4 wb = *(const float4*)&w2s[k * HH + j0 + 4];
        acc[0] += a * wa.x; acc[1] += a * wa.y; acc[2] += a * wa.z; acc[3] += a * wa.w;
        acc[4] += a * wb.x; acc[5] += a * wb.y; acc[6] += a * wb.z; acc[7] += a * wb.w;
    }
    int node = n0 + nn;
    if (node < NN) {
        *(float4*)&g_bufA[node * HH + j0]     = make_float4(acc[0], acc[1], acc[2], acc[3]);
        *(float4*)&g_bufA[node * HH + j0 + 4] = make_float4(acc[4], acc[5], acc[6], acc[7]);
    }
}

// ---------------- GraphNorm stats: per-graph sum and sumsq ----------------
__global__ void k_stats() {
    int b = blockIdx.x;
    int s = g_gstart[b], e = g_gstart[b + 1];
    int tid = threadIdx.x;
    int c = tid & 63, l = tid >> 6;
    float as = 0.f, aq = 0.f;
    for (int n = s + l; n < e; n += 4) {
        float v = g_bufA[n * HH + c];
        as += v; aq += v * v;
    }
    __shared__ float ss[256], sq[256];
    ss[tid] = as; sq[tid] = aq;
    __syncthreads();
    if (tid < 64) {
        float ts_ = ss[tid] + ss[tid + 64] + ss[tid + 128] + ss[tid + 192];
        float tq = sq[tid] + sq[tid + 64] + sq[tid + 128] + sq[tid + 192];
        g_ssum[b * HH + tid] = ts_;
        g_ssq[b * HH + tid] = tq;
    }
}

// ---------------- GraphNorm precompute: per-(graph,channel) scale/shift ----------------
__global__ void k_nprep(const float* __restrict__ gw, const float* __restrict__ gb,
                        const float* __restrict__ gms) {
    int idx = blockIdx.x * blockDim.x + threadIdx.x;
    if (idx >= BB * HH) return;
    int b = idx >> 6, c = idx & 63;
    float cnt = fmaxf((float)(g_gstart[b + 1] - g_gstart[b]), 1.f);
    float mean = g_ssum[idx] / cnt;
    float ex2 = g_ssq[idx] / cnt;
    float ms = gms[c];
    float var = ex2 - (2.f * ms - ms * ms) * mean * mean;
    float sc = rsqrtf(var + GN_EPS) * gw[c];
    g_scale[idx] = sc;
    g_shift[idx] = gb[c] - ms * mean * sc;
}

// ---------------- GraphNorm apply + ReLU + residual accumulate ----------------
__global__ void k_apply(const int* __restrict__ batch, int accum) {
    int i4 = blockIdx.x * blockDim.x + threadIdx.x;
    if (i4 >= NN * (HH / 4)) return;
    int node = i4 >> 4;
    int c0 = (i4 & 15) * 4;
    int g = batch[node];
    const float4 v = *(const float4*)&g_bufA[i4 * 4];
    const float4 sc = *(const float4*)&g_scale[g * HH + c0];
    const float4 sh = *(const float4*)&g_shift[g * HH + c0];
    float4 o;
    o.x = fmaxf(v.x * sc.x + sh.x, 0.f);
    o.y = fmaxf(v.y * sc.y + sh.y, 0.f);
    o.z = fmaxf(v.z * sc.z + sh.z, 0.f);
    o.w = fmaxf(v.w * sc.w + sh.w, 0.f);
    *(float4*)&g_hcur[i4 * 4] = o;
    if (accum) {
        float4 hs = *(const float4*)&g_hsum[i4 * 4];
        hs.x += o.x; hs.y += o.y; hs.z += o.z; hs.w += o.w;
        *(float4*)&g_hsum[i4 * 4] = hs;
    } else {
        *(float4*)&g_hsum[i4 * 4] = o;
    }
}

// ---------------- gate logits ----------------
__global__ void k_gate(const float* __restrict__ gw, const float* __restrict__ gb) {
    int gwarp = (blockIdx.x * blockDim.x + threadIdx.x) >> 5;
    int lane = threadIdx.x & 31;
    if (gwarp >= NN) return;
    int n = gwarp;
    float a = g_hsum[n * HH + lane] * gw[lane] + g_hsum[n * HH + 32 + lane] * gw[lane + 32];
    #pragma unroll
    for (int off = 16; off; off >>= 1) a += __shfl_down_sync(0xffffffffu, a, off);
    if (lane == 0) g_gate[n] = a + gb[0];
}

// ---------------- pooling: attention softmax + mean + max per graph ----------------
__global__ void k_pool() {
    int b = blockIdx.x;
    int s = g_gstart[b], e = g_gstart[b + 1];
    int tid = threadIdx.x;
    __shared__ float red[256];
    __shared__ float red2[256];
    __shared__ float red3[256];
    __shared__ float sM, sD;

    // pass A: max gate
    float m = -INFINITY;
    for (int n = s + tid; n < e; n += 256) m = fmaxf(m, g_gate[n]);
    red[tid] = m;
    __syncthreads();
    for (int o = 128; o > 0; o >>= 1) {
        if (tid < o) red[tid] = fmaxf(red[tid], red[tid + o]);
        __syncthreads();
    }
    if (tid == 0) sM = red[0];
    __syncthreads();
    float mm = sM;

    // pass B: sum exp
    float d = 0.f;
    for (int n = s + tid; n < e; n += 256) d += expf(g_gate[n] - mm);
    __syncthreads();
    red[tid] = d;
    __syncthreads();
    for (int o = 128; o > 0; o >>= 1) {
        if (tid < o) red[tid] += red[tid + o];
        __syncthreads();
    }
    if (tid == 0) sD = red[0];
    __syncthreads();
    float den = sD;

    // pass C: att / mean / max accumulate
    int c = tid & 63, l = tid >> 6;
    float fa = 0.f, fm = 0.f, fx = -INFINITY;
    for (int n = s + l; n < e; n += 4) {
        float hv = g_hsum[n * HH + c];
        float w = expf(g_gate[n] - mm);
        fa += w * hv; fm += hv; fx = fmaxf(fx, hv);
    }
    __syncthreads();
    red[tid] = fa; red2[tid] = fm; red3[tid] = fx;
    __syncthreads();
    if (tid < 64) {
        float ta = red[tid] + red[tid + 64] + red[tid + 128] + red[tid + 192];
        float tm = red2[tid] + red2[tid + 64] + red2[tid + 128] + red2[tid + 192];
        float tx = fmaxf(fmaxf(red3[tid], red3[tid + 64]), fmaxf(red3[tid + 128], red3[tid + 192]));
        float cnt = fmaxf((float)(e - s), 1.f);
        g_att[b * HH + tid] = (e > s) ? (ta / den) : 0.f;
        g_meanp[b * HH + tid] = tm / cnt;
        g_maxp[b * HH + tid] = tx;
    }
}

// ---------------- head ----------------
__global__ void k_head(const float* __restrict__ u,
                       const float* __restrict__ hw1, const float* __restrict__ hb1,
                       const float* __restrict__ hw2, const float* __restrict__ hb2,
                       float* __restrict__ out) {
    int b = blockIdx.x;
    int tid = threadIdx.x;  // 64 threads
    __shared__ float z[3 * HH + 4];
    z[tid] = g_att[b * HH + tid];
    z[HH + tid] = g_meanp[b * HH + tid];
    z[2 * HH + tid] = g_maxp[b * HH + tid];
    if (tid < 3) z[3 * HH + tid] = u[b * 3 + tid];
    __syncthreads();
    float a = hb1[tid];
    #pragma unroll 5
    for (int k = 0; k < 3 * HH + 3; k++) a += z[k] * hw1[k * HH + tid];
    float v = fmaxf(a, 0.f) * hw2[tid];
    __shared__ float rr[64];
    rr[tid] = v;
    __syncthreads();
    if (tid < 32) {
        float t = rr[tid] + rr[tid + 32];
        #pragma unroll
        for (int off = 16; off; off >>= 1) t += __shfl_down_sync(0xffffffffu, t, off);
        if (tid == 0) out[b] = t + hb2[0];
    }
}

// ---------------- launch ----------------
extern "C" void kernel_launch(void* const* d_in, const int* in_sizes, int n_in,
                              void* d_out, int out_size) {
    const float* x = (const float*)d_in[0];
    const int* ei = (const int*)d_in[1];
    const int* batch = (const int*)d_in[2];
    const float* u = (const float*)d_in[3];
    const float *wA[3], *bA[3], *wB[3], *bB[3], *gnw[3], *gnb[3], *gnms[3];
    int p = 4;
    for (int l = 0; l < 3; l++) {
        wA[l] = (const float*)d_in[p++]; bA[l] = (const float*)d_in[p++];
        wB[l] = (const float*)d_in[p++]; bB[l] = (const float*)d_in[p++];
        gnw[l] = (const float*)d_in[p++]; gnb[l] = (const float*)d_in[p++];
        gnms[l] = (const float*)d_in[p++];
    }
    const float* gate_w = (const float*)d_in[p++];
    const float* gate_b = (const float*)d_in[p++];
    const float* hw1 = (const float*)d_in[p++];
    const float* hb1 = (const float*)d_in[p++];
    const float* hw2 = (const float*)d_in[p++];
    const float* hb2 = (const float*)d_in[p++];
    float* out = (float*)d_out;

    // CSR build (by destination)
    k_zero<<<(NN + 255) / 256, 256>>>();
    k_hist<<<(EE + 255) / 256, 256>>>(ei);
    k_scan1<<<SCAN_NBLK, 1024>>>();
    k_scan2<<<1, 32>>>();
    k_scan3<<<(NN + 255) / 256, 256>>>();
    k_fill<<<(EE + 255) / 256, 256>>>(ei);
    k_gstart<<<1, 256>>>(batch);

    // trunk: 3x (GIN agg -> MLP -> GraphNorm stats/prep/apply + residual)
    for (int l = 0; l < 3; l++) {
        k_agg<<<(NN + 7) / 8, 256>>>(x, l == 0 ? 1 : 0);
        k_mlp<<<(NN + 31) / 32, 256>>>(wA[l], bA[l], wB[l], bB[l]);
        k_stats<<<BB, 256>>>();
        k_nprep<<<(BB * HH + 255) / 256, 256>>>(gnw[l], gnb[l], gnms[l]);
        k_apply<<<(NN * (HH / 4) + 255) / 256, 256>>>(batch, l == 0 ? 0 : 1);
    }

    // pooling + head
    k_gate<<<(NN + 7) / 8, 256>>>(gate_w, gate_b);
    k_pool<<<BB, 256>>>();
    k_head<<<BB, 64>>>(u, hw1, hb1, hw2, hb2, out);
    (void)in_sizes; (void)n_in; (void)out_size;
}

// round 6
// speedup vs baseline: 1.1008x; 1.1008x over previous
#include <cuda_runtime.h>
#include <math.h>

#define NN 100000
#define EE 1200000
#define BB 128
#define HH 64
#define GN_EPS 1e-5f
#define SCAN_NBLK ((NN + 1023) / 1024)
#define TS 68   // padded tile stride (floats) -> conflict-free scalar LDS

// ---------------- device scratch ----------------
__device__ __align__(16) int   g_counts[NN];
__device__ __align__(16) int   g_rowptr[NN];
__device__ __align__(16) int   g_wrptr[NN];    // write cursor; == row end after fill
__device__ __align__(16) int   g_col[EE];
__device__ __align__(16) int   g_blocksum[SCAN_NBLK + 1];
__device__ __align__(16) int   g_blockoff[SCAN_NBLK + 1];
__device__ __align__(16) int   g_gstart[BB + 1];
__device__ __align__(16) float g_bufA[NN * HH];   // pre-norm MLP output
__device__ __align__(16) float g_hcur[NN * HH];   // current layer output (post-norm)
__device__ __align__(16) float g_hsum[NN * HH];   // residual sum
__device__ __align__(16) float g_ssum[BB * HH];
__device__ __align__(16) float g_ssq[BB * HH];
__device__ __align__(16) float g_scale[BB * HH];
__device__ __align__(16) float g_shift[BB * HH];
__device__ __align__(16) float g_gate[NN];

// ---------------- CSR build ----------------
__global__ void k_zero() {
    int i = blockIdx.x * blockDim.x + threadIdx.x;
    if (i < NN) g_counts[i] = 0;
    if (i < BB * HH) { g_ssum[i] = 0.f; g_ssq[i] = 0.f; }
}

__global__ void k_hist(const int* __restrict__ ei) {
    int e = blockIdx.x * blockDim.x + threadIdx.x;
    if (e < EE) atomicAdd(&g_counts[ei[EE + e]], 1);
}

__global__ void k_scan1() {
    __shared__ int s[1024];
    int tid = threadIdx.x;
    int i = blockIdx.x * 1024 + tid;
    int v = (i < NN) ? g_counts[i] : 0;
    s[tid] = v;
    __syncthreads();
    for (int off = 1; off < 1024; off <<= 1) {
        int t = (tid >= off) ? s[tid - off] : 0;
        __syncthreads();
        s[tid] += t;
        __syncthreads();
    }
    if (i < NN) g_rowptr[i] = s[tid] - v;      // exclusive
    if (tid == 1023) g_blocksum[blockIdx.x] = s[1023];
}

// block 0: parallel scan over per-block sums; block 1: per-graph start offsets
__global__ void k_scan2_gstart(const int* __restrict__ batch) {
    if (blockIdx.x == 0) {
        __shared__ int s[256];
        int tid = threadIdx.x;
        int v = (tid < SCAN_NBLK) ? g_blocksum[tid] : 0;
        s[tid] = v;
        __syncthreads();
        for (int off = 1; off < 256; off <<= 1) {
            int t = (tid >= off) ? s[tid - off] : 0;
            __syncthreads();
            s[tid] += t;
            __syncthreads();
        }
        if (tid < SCAN_NBLK) g_blockoff[tid] = s[tid] - v;  // exclusive
    } else {
        int b = threadIdx.x;
        if (b > BB) return;
        if (b == BB) { g_gstart[BB] = NN; return; }
        int lo = 0, hi = NN;
        while (lo < hi) {
            int mid = (lo + hi) >> 1;
            if (batch[mid] < b) lo = mid + 1; else hi = mid;
        }
        g_gstart[b] = lo;
    }
}

__global__ void k_scan3() {
    int i = blockIdx.x * blockDim.x + threadIdx.x;
    if (i < NN) {
        int v = g_rowptr[i] + g_blockoff[i >> 10];
        g_rowptr[i] = v;
        g_wrptr[i] = v;
    }
}

__global__ void k_fill(const int* __restrict__ ei) {
    int e = blockIdx.x * blockDim.x + threadIdx.x;
    if (e < EE) {
        int dst = ei[EE + e];
        int pos = atomicAdd(&g_wrptr[dst], 1);
        g_col[pos] = ei[e];
    }
}

// ---------------- fused layer: GIN agg -> MLP -> per-graph stats atomics ----------------
// 256 threads, 32 nodes per block. NN % 32 == 0, so no bounds checks.
__global__ void __launch_bounds__(256) k_layer(
        const float* __restrict__ xin, int use_x,
        const float* __restrict__ W1, const float* __restrict__ B1,
        const float* __restrict__ W2, const float* __restrict__ B2,
        const int* __restrict__ batch) {
    __shared__ __align__(16) float w1s[HH * HH];
    __shared__ __align__(16) float w2s[HH * HH];
    __shared__ __align__(16) float ts[32 * TS];
    __shared__ float b1s[HH], b2s[HH];
    __shared__ float rs_[256], rq_[256];
    int tid = threadIdx.x;
    int warp = tid >> 5, lane = tid & 31;
    int n0 = blockIdx.x * 32;

    for (int i = tid; i < HH * HH; i += 256) { w1s[i] = W1[i]; w2s[i] = W2[i]; }
    if (tid < HH) { b1s[tid] = B1[tid]; b2s[tid] = B2[tid]; }

    // ---- aggregation: warp per node (4 nodes per warp), float2 lanes ----
    const float2* __restrict__ inp = use_x ? (const float2*)xin : (const float2*)g_hcur;
    #pragma unroll
    for (int i = 0; i < 4; i++) {
        int node = n0 + warp * 4 + i;
        float2 acc = inp[node * 32 + lane];
        int e = g_rowptr[node];
        int re = g_wrptr[node];
        for (; e + 4 <= re; e += 4) {
            int s0 = g_col[e], s1 = g_col[e + 1], s2 = g_col[e + 2], s3 = g_col[e + 3];
            float2 v0 = inp[s0 * 32 + lane];
            float2 v1 = inp[s1 * 32 + lane];
            float2 v2 = inp[s2 * 32 + lane];
            float2 v3 = inp[s3 * 32 + lane];
            acc.x += (v0.x + v1.x) + (v2.x + v3.x);
            acc.y += (v0.y + v1.y) + (v2.y + v3.y);
        }
        for (; e < re; e++) {
            int s = g_col[e];
            float2 v = inp[s * 32 + lane];
            acc.x += v.x; acc.y += v.y;
        }
        int r = node - n0;
        *(float2*)&ts[r * TS + lane * 2] = acc;
    }
    __syncthreads();

    // ---- MLP ----
    int nn = tid >> 3;            // node within tile (0..31)
    int j0 = (tid & 7) * 8;       // output channel group
    float acc[8];

    // GEMM 1 + ReLU (results buffered in regs, then written back to ts)
    #pragma unroll
    for (int j = 0; j < 8; j++) acc[j] = b1s[j0 + j];
    #pragma unroll 8
    for (int k = 0; k < HH; k++) {
        float a = ts[nn * TS + k];
        float4 wa = *(const float4*)&w1s[k * HH + j0];
        float4 wb = *(const float4*)&w1s[k * HH + j0 + 4];
        acc[0] += a * wa.x; acc[1] += a * wa.y; acc[2] += a * wa.z; acc[3] += a * wa.w;
        acc[4] += a * wb.x; acc[5] += a * wb.y; acc[6] += a * wb.z; acc[7] += a * wb.w;
    }
    __syncthreads();
    #pragma unroll
    for (int j = 0; j < 8; j++) ts[nn * TS + j0 + j] = fmaxf(acc[j], 0.f);
    __syncthreads();

    // GEMM 2
    #pragma unroll
    for (int j = 0; j < 8; j++) acc[j] = b2s[j0 + j];
    #pragma unroll 8
    for (int k = 0; k < HH; k++) {
        float a = ts[nn * TS + k];
        float4 wa = *(const float4*)&w2s[k * HH + j0];
        float4 wb = *(const float4*)&w2s[k * HH + j0 + 4];
        acc[0] += a * wa.x; acc[1] += a * wa.y; acc[2] += a * wa.z; acc[3] += a * wa.w;
        acc[4] += a * wb.x; acc[5] += a * wb.y; acc[6] += a * wb.z; acc[7] += a * wb.w;
    }
    int node = n0 + nn;
    *(float4*)&g_bufA[node * HH + j0]     = make_float4(acc[0], acc[1], acc[2], acc[3]);
    *(float4*)&g_bufA[node * HH + j0 + 4] = make_float4(acc[4], acc[5], acc[6], acc[7]);

    // ---- fused GraphNorm stats (block reduce per graph -> global atomics) ----
    __syncthreads();
    #pragma unroll
    for (int j = 0; j < 8; j++) ts[nn * TS + j0 + j] = acc[j];
    __syncthreads();

    int gfirst = batch[n0], glast = batch[n0 + 31];
    int c = tid & 63, sub = tid >> 6;
    for (int g = gfirst; g <= glast; g++) {
        int lo = max(n0, g_gstart[g]);
        int hi = min(n0 + 32, g_gstart[g + 1]);
        float s = 0.f, q = 0.f;
        for (int n = lo + sub; n < hi; n += 4) {
            float vv = ts[(n - n0) * TS + c];
            s += vv; q += vv * vv;
        }
        rs_[tid] = s; rq_[tid] = q;
        __syncthreads();
        if (tid < 64) {
            float ts2 = rs_[tid] + rs_[tid + 64] + rs_[tid + 128] + rs_[tid + 192];
            float tq2 = rq_[tid] + rq_[tid + 64] + rq_[tid + 128] + rq_[tid + 192];
            atomicAdd(&g_ssum[g * HH + tid], ts2);
            atomicAdd(&g_ssq[g * HH + tid], tq2);
        }
        __syncthreads();
    }
}

// ---------------- GraphNorm precompute (+ zero stats for next layer) ----------------
__global__ void k_nprep(const float* __restrict__ gw, const float* __restrict__ gb,
                        const float* __restrict__ gms) {
    int idx = blockIdx.x * blockDim.x + threadIdx.x;
    if (idx >= BB * HH) return;
    int b = idx >> 6, c = idx & 63;
    float cnt = fmaxf((float)(g_gstart[b + 1] - g_gstart[b]), 1.f);
    float mean = g_ssum[idx] / cnt;
    float ex2 = g_ssq[idx] / cnt;
    float ms = gms[c];
    float var = ex2 - (2.f * ms - ms * ms) * mean * mean;
    float sc = rsqrtf(var + GN_EPS) * gw[c];
    g_scale[idx] = sc;
    g_shift[idx] = gb[c] - ms * mean * sc;
    g_ssum[idx] = 0.f;
    g_ssq[idx] = 0.f;
}

// ---------------- GraphNorm apply + ReLU + residual (layers 1,2) ----------------
__global__ void k_apply(const int* __restrict__ batch, int accum) {
    int i4 = blockIdx.x * blockDim.x + threadIdx.x;
    if (i4 >= NN * (HH / 4)) return;
    int node = i4 >> 4;
    int c0 = (i4 & 15) * 4;
    int g = batch[node];
    const float4 v = *(const float4*)&g_bufA[i4 * 4];
    const float4 sc = *(const float4*)&g_scale[g * HH + c0];
    const float4 sh = *(const float4*)&g_shift[g * HH + c0];
    float4 o;
    o.x = fmaxf(v.x * sc.x + sh.x, 0.f);
    o.y = fmaxf(v.y * sc.y + sh.y, 0.f);
    o.z = fmaxf(v.z * sc.z + sh.z, 0.f);
    o.w = fmaxf(v.w * sc.w + sh.w, 0.f);
    *(float4*)&g_hcur[i4 * 4] = o;
    if (accum) {
        float4 hs = *(const float4*)&g_hsum[i4 * 4];
        hs.x += o.x; hs.y += o.y; hs.z += o.z; hs.w += o.w;
        *(float4*)&g_hsum[i4 * 4] = hs;
    } else {
        *(float4*)&g_hsum[i4 * 4] = o;
    }
}

// ---------------- layer-3 apply: norm + ReLU + residual + gate logits (no hcur) ----------------
__global__ void k_apply_gate(const int* __restrict__ batch,
                             const float* __restrict__ gw, const float* __restrict__ gb) {
    int t = blockIdx.x * blockDim.x + threadIdx.x;
    if (t >= NN * 16) return;
    int node = t >> 4;
    int c0 = (t & 15) * 4;
    int g = batch[node];
    const float4 v = *(const float4*)&g_bufA[t * 4];
    const float4 sc = *(const float4*)&g_scale[g * HH + c0];
    const float4 sh = *(const float4*)&g_shift[g * HH + c0];
    float4 o;
    o.x = fmaxf(v.x * sc.x + sh.x, 0.f);
    o.y = fmaxf(v.y * sc.y + sh.y, 0.f);
    o.z = fmaxf(v.z * sc.z + sh.z, 0.f);
    o.w = fmaxf(v.w * sc.w + sh.w, 0.f);
    float4 hs = *(const float4*)&g_hsum[t * 4];
    hs.x += o.x; hs.y += o.y; hs.z += o.z; hs.w += o.w;
    *(float4*)&g_hsum[t * 4] = hs;
    const float4 w = *(const float4*)&gw[c0];
    float d = hs.x * w.x + hs.y * w.y + hs.z * w.z + hs.w * w.w;
    d += __shfl_down_sync(0xffffffffu, d, 8, 16);
    d += __shfl_down_sync(0xffffffffu, d, 4, 16);
    d += __shfl_down_sync(0xffffffffu, d, 2, 16);
    d += __shfl_down_sync(0xffffffffu, d, 1, 16);
    if ((t & 15) == 0) g_gate[node] = d + gb[0];
}

// ---------------- fused pooling (att softmax + mean + max) + head MLP ----------------
__global__ void k_pool_head(const float* __restrict__ u,
                            const float* __restrict__ hw1, const float* __restrict__ hb1,
                            const float* __restrict__ hw2, const float* __restrict__ hb2,
                            float* __restrict__ out) {
    int b = blockIdx.x;
    int s = g_gstart[b], e = g_gstart[b + 1];
    int tid = threadIdx.x;
    __shared__ float red[256], red2[256], red3[256];
    __shared__ float za[64], zm[64], zx[64], rr[64];
    __shared__ float sM, sD;

    // pass A: max gate
    float m = -INFINITY;
    for (int n = s + tid; n < e; n += 256) m = fmaxf(m, g_gate[n]);
    red[tid] = m;
    __syncthreads();
    for (int o = 128; o > 0; o >>= 1) {
        if (tid < o) red[tid] = fmaxf(red[tid], red[tid + o]);
        __syncthreads();
    }
    if (tid == 0) sM = red[0];
    __syncthreads();
    float mm = sM;

    // pass B: sum exp
    float d = 0.f;
    for (int n = s + tid; n < e; n += 256) d += __expf(g_gate[n] - mm);
    __syncthreads();
    red[tid] = d;
    __syncthreads();
    for (int o = 128; o > 0; o >>= 1) {
        if (tid < o) red[tid] += red[tid + o];
        __syncthreads();
    }
    if (tid == 0) sD = red[0];
    __syncthreads();
    float den = sD;

    // pass C: att / mean / max
    int c = tid & 63, l = tid >> 6;
    float fa = 0.f, fm = 0.f, fx = -INFINITY;
    for (int n = s + l; n < e; n += 4) {
        float hv = g_hsum[n * HH + c];
        float w = __expf(g_gate[n] - mm);
        fa += w * hv; fm += hv; fx = fmaxf(fx, hv);
    }
    __syncthreads();
    red[tid] = fa; red2[tid] = fm; red3[tid] = fx;
    __syncthreads();
    if (tid < 64) {
        float ta = red[tid] + red[tid + 64] + red[tid + 128] + red[tid + 192];
        float tm = red2[tid] + red2[tid + 64] + red2[tid + 128] + red2[tid + 192];
        float tx = fmaxf(fmaxf(red3[tid], red3[tid + 64]), fmaxf(red3[tid + 128], red3[tid + 192]));
        float cnt = fmaxf((float)(e - s), 1.f);
        za[tid] = (e > s) ? (ta / den) : 0.f;
        zm[tid] = tm / cnt;
        zx[tid] = tx;
    }
    __syncthreads();

    // head: 64 active threads, one output channel each
    if (tid < 64) {
        float a = hb1[tid];
        #pragma unroll 4
        for (int k = 0; k < HH; k++) a += za[k] * hw1[k * HH + tid];
        #pragma unroll 4
        for (int k = 0; k < HH; k++) a += zm[k] * hw1[(HH + k) * HH + tid];
        #pragma unroll 4
        for (int k = 0; k < HH; k++) a += zx[k] * hw1[(2 * HH + k) * HH + tid];
        #pragma unroll
        for (int k = 0; k < 3; k++) a += u[b * 3 + k] * hw1[(3 * HH + k) * HH + tid];
        rr[tid] = fmaxf(a, 0.f) * hw2[tid];
    }
    __syncthreads();
    if (tid == 0) {
        float t = 0.f;
        for (int k = 0; k < 64; k++) t += rr[k];
        out[b] = t + hb2[0];
    }
}

// ---------------- launch ----------------
extern "C" void kernel_launch(void* const* d_in, const int* in_sizes, int n_in,
                              void* d_out, int out_size) {
    const float* x = (const float*)d_in[0];
    const int* ei = (const int*)d_in[1];
    const int* batch = (const int*)d_in[2];
    const float* u = (const float*)d_in[3];
    const float *wA[3], *bA[3], *wB[3], *bB[3], *gnw[3], *gnb[3], *gnms[3];
    int p = 4;
    for (int l = 0; l < 3; l++) {
        wA[l] = (const float*)d_in[p++]; bA[l] = (const float*)d_in[p++];
        wB[l] = (const float*)d_in[p++]; bB[l] = (const float*)d_in[p++];
        gnw[l] = (const float*)d_in[p++]; gnb[l] = (const float*)d_in[p++];
        gnms[l] = (const float*)d_in[p++];
    }
    const float* gate_w = (const float*)d_in[p++];
    const float* gate_b = (const float*)d_in[p++];
    const float* hw1 = (const float*)d_in[p++];
    const float* hb1 = (const float*)d_in[p++];
    const float* hw2 = (const float*)d_in[p++];
    const float* hb2 = (const float*)d_in[p++];
    float* out = (float*)d_out;

    // CSR build (by destination)
    k_zero<<<(NN + 255) / 256, 256>>>();
    k_hist<<<(EE + 255) / 256, 256>>>(ei);
    k_scan1<<<SCAN_NBLK, 1024>>>();
    k_scan2_gstart<<<2, 256>>>(batch);
    k_scan3<<<(NN + 255) / 256, 256>>>();
    k_fill<<<(EE + 255) / 256, 256>>>(ei);

    // trunk: 3x (fused agg+MLP+stats -> nprep -> apply)
    for (int l = 0; l < 3; l++) {
        k_layer<<<NN / 32, 256>>>(x, l == 0 ? 1 : 0, wA[l], bA[l], wB[l], bB[l], batch);
        k_nprep<<<(BB * HH + 255) / 256, 256>>>(gnw[l], gnb[l], gnms[l]);
        if (l < 2)
            k_apply<<<(NN * 16) / 256, 256>>>(batch, l == 0 ? 0 : 1);
        else
            k_apply_gate<<<(NN * 16) / 256, 256>>>(batch, gate_w, gate_b);
    }

    // fused pooling + head
    k_pool_head<<<BB, 256>>>(u, hw1, hb1, hw2, hb2, out);
    (void)in_sizes; (void)n_in; (void)out_size;
}

// round 11
// speedup vs baseline: 2.6367x; 2.3951x over previous
#include <cuda_runtime.h>
#include <cuda_fp16.h>
#include <stdint.h>
#include <math.h>

#define NN 100000
#define EE 1200000
#define BB 128
#define HH 64
#define GN_EPS 1e-5f
#define SCAN_NBLK ((NN + 1023) / 1024)

// ---------------- device scratch ----------------
__device__ __align__(16) int   g_counts[NN];
__device__ __align__(16) int   g_rowptr[NN];
__device__ __align__(16) int   g_wrptr[NN];
__device__ __align__(16) int   g_col[EE];
__device__ __align__(16) int   g_blocksum[SCAN_NBLK + 1];
__device__ __align__(16) int   g_blockoff[SCAN_NBLK + 1];
__device__ __align__(16) int   g_gstart[BB + 1];
__device__ __align__(16) float g_hcur[NN * HH];   // post-norm layer output (fp32)
__device__ __align__(16) float g_bufA[NN * HH];   // pre-norm MLP output (fp32)
__device__ __align__(16) float g_hsum[NN * HH];   // residual sum (fp32)
__device__ __align__(16) float g_ssum[BB * HH];
__device__ __align__(16) float g_ssq[BB * HH];
__device__ __align__(16) float g_scale[BB * HH];
__device__ __align__(16) float g_shift[BB * HH];
__device__ __align__(16) float g_gate[NN];

// ---------------- MMA helpers ----------------
__device__ __forceinline__ void ldmx4(uint32_t& r0, uint32_t& r1, uint32_t& r2, uint32_t& r3,
                                      uint32_t addr) {
    asm volatile("ldmatrix.sync.aligned.m8n8.x4.shared.b16 {%0,%1,%2,%3}, [%4];"
                 : "=r"(r0), "=r"(r1), "=r"(r2), "=r"(r3) : "r"(addr));
}
__device__ __forceinline__ void ldmx4t(uint32_t& r0, uint32_t& r1, uint32_t& r2, uint32_t& r3,
                                       uint32_t addr) {
    asm volatile("ldmatrix.sync.aligned.m8n8.x4.trans.shared.b16 {%0,%1,%2,%3}, [%4];"
                 : "=r"(r0), "=r"(r1), "=r"(r2), "=r"(r3) : "r"(addr));
}
__device__ __forceinline__ void mma16816(float& c0, float& c1, float& c2, float& c3,
                                         uint32_t a0, uint32_t a1, uint32_t a2, uint32_t a3,
                                         uint32_t b0, uint32_t b1) {
    asm volatile("mma.sync.aligned.m16n8k16.row.col.f32.f16.f16.f32 "
                 "{%0,%1,%2,%3}, {%4,%5,%6,%7}, {%8,%9}, {%0,%1,%2,%3};"
                 : "+f"(c0), "+f"(c1), "+f"(c2), "+f"(c3)
                 : "r"(a0), "r"(a1), "r"(a2), "r"(a3), "r"(b0), "r"(b1));
}
// split float -> (hi, lo) fp16
__device__ __forceinline__ void split_h(float v, __half& hi, __half& lo) {
    hi = __float2half(v);
    lo = __float2half(v - __half2float(hi));
}

// ---------------- CSR build ----------------
__global__ void k_zero() {
    int i = blockIdx.x * blockDim.x + threadIdx.x;
    if (i < NN) g_counts[i] = 0;
    if (i < BB * HH) { g_ssum[i] = 0.f; g_ssq[i] = 0.f; }
}

__global__ void k_hist(const int* __restrict__ ei) {
    int e = blockIdx.x * blockDim.x + threadIdx.x;
    if (e < EE) atomicAdd(&g_counts[ei[EE + e]], 1);
}

__global__ void k_scan1() {
    __shared__ int s[1024];
    int tid = threadIdx.x;
    int i = blockIdx.x * 1024 + tid;
    int v = (i < NN) ? g_counts[i] : 0;
    s[tid] = v;
    __syncthreads();
    for (int off = 1; off < 1024; off <<= 1) {
        int t = (tid >= off) ? s[tid - off] : 0;
        __syncthreads();
        s[tid] += t;
        __syncthreads();
    }
    if (i < NN) g_rowptr[i] = s[tid] - v;      // exclusive
    if (tid == 1023) g_blocksum[blockIdx.x] = s[1023];
}

__global__ void k_scan2() {
    __shared__ int s[128];
    int tid = threadIdx.x;
    int v = (tid < SCAN_NBLK) ? g_blocksum[tid] : 0;
    s[tid] = v;
    __syncthreads();
    for (int off = 1; off < 128; off <<= 1) {
        int t = (tid >= off) ? s[tid - off] : 0;
        __syncthreads();
        s[tid] += t;
        __syncthreads();
    }
    if (tid < SCAN_NBLK) g_blockoff[tid] = s[tid] - v;  // exclusive
}

// scan finalize + per-graph start boundaries
__global__ void k_scan3(const int* __restrict__ batch) {
    int i = blockIdx.x * blockDim.x + threadIdx.x;
    if (i >= NN) return;
    int v = g_rowptr[i] + g_blockoff[i >> 10];
    g_rowptr[i] = v;
    g_wrptr[i] = v;
    int bc = batch[i];
    int bp = (i == 0) ? -1 : batch[i - 1];
    for (int g = bp + 1; g <= bc; g++) g_gstart[g] = i;
    if (i == NN - 1)
        for (int g = bc + 1; g <= BB; g++) g_gstart[g] = NN;
}

__global__ void k_fill(const int* __restrict__ ei) {
    int e = blockIdx.x * blockDim.x + threadIdx.x;
    if (e < EE) {
        int dst = ei[EE + e];
        int pos = atomicAdd(&g_wrptr[dst], 1);
        g_col[pos] = ei[e];
    }
}

// ---------------- fused layer: fp32 GIN agg -> split-fp16 HMMA MLP -> stats ----------------
// 256 threads (8 warps), 64 nodes per block. Split-fp16: D = Ah*Wh + Ah*Wl + Al*Wh (fp32 acc)
__global__ void __launch_bounds__(256) k_layer(
        const float* __restrict__ xin, int use_x,
        const float* __restrict__ W1, const float* __restrict__ B1,
        const float* __restrict__ W2, const float* __restrict__ B2,
        const int* __restrict__ batch) {
    __shared__ __align__(16) __half wh_[HH * 72];   // current weight hi (W1 then W2)
    __shared__ __align__(16) __half wl_[HH * 72];   // current weight lo
    __shared__ __align__(16) unsigned char u_area[64 * 72 * 2 * 2];  // {ah, al} / o_f union
    __shared__ float b1s[HH], b2s[HH];
    __shared__ float rs_[256], rq_[256];
    __half* ah_ = (__half*)u_area;                  // 64 x 72 hi
    __half* al_ = (__half*)(u_area + 64 * 72 * 2);  // 64 x 72 lo
    float*  o_f = (float*)u_area;                   // 64 x 65 (reused after GEMM2)

    int tid = threadIdx.x;
    int warp = tid >> 5, lane = tid & 31;
    int n0 = blockIdx.x * 64;

    // W1 -> smem (split); W2 -> register stash (split, written to smem after GEMM1)
    for (int i = tid; i < HH * HH; i += 256) {
        int k = i >> 6, n = i & 63;
        split_h(W1[i], wh_[k * 72 + n], wl_[k * 72 + n]);
    }
    uint32_t w2h_st[8], w2l_st[8];
    {
        int i0 = tid * 16;
        #pragma unroll
        for (int j = 0; j < 8; j++) {
            float2 v = *(const float2*)&W2[i0 + j * 2];
            __half h0, l0, h1, l1;
            split_h(v.x, h0, l0);
            split_h(v.y, h1, l1);
            __half2 hh = __halves2half2(h0, h1), ll = __halves2half2(l0, l1);
            w2h_st[j] = *(uint32_t*)&hh;
            w2l_st[j] = *(uint32_t*)&ll;
        }
    }
    if (tid < HH) { b1s[tid] = B1[tid]; b2s[tid] = B2[tid]; }

    // ---- aggregation: warp per node (8 nodes/warp), fp32, split into ah/al ----
    const float2* __restrict__ inp = use_x ? (const float2*)xin : (const float2*)g_hcur;
    #pragma unroll
    for (int i = 0; i < 8; i++) {
        int node = n0 + warp * 8 + i;
        int r = warp * 8 + i;
        float ax = 0.f, ay = 0.f;
        if (node < NN) {
            float2 f = inp[node * 32 + lane];
            ax = f.x; ay = f.y;
            int e = g_rowptr[node];
            int re = g_wrptr[node];
            for (; e + 4 <= re; e += 4) {
                int s0 = g_col[e], s1 = g_col[e + 1], s2 = g_col[e + 2], s3 = g_col[e + 3];
                float2 v0 = inp[s0 * 32 + lane];
                float2 v1 = inp[s1 * 32 + lane];
                float2 v2 = inp[s2 * 32 + lane];
                float2 v3 = inp[s3 * 32 + lane];
                ax += (v0.x + v1.x) + (v2.x + v3.x);
                ay += (v0.y + v1.y) + (v2.y + v3.y);
            }
            for (; e < re; e++) {
                float2 v = inp[g_col[e] * 32 + lane];
                ax += v.x; ay += v.y;
            }
        }
        __half hx, lx, hy, ly;
        split_h(ax, hx, lx);
        split_h(ay, hy, ly);
        __half2 hh = __halves2half2(hx, hy), ll = __halves2half2(lx, ly);
        ((__half2*)(ah_ + r * 72))[lane] = hh;
        ((__half2*)(al_ + r * 72))[lane] = ll;
    }
    __syncthreads();

    // ---- MMA setup ----
    int mw = warp & 3;            // 16-row block
    int nw = warp >> 2;           // 32-col block
    int row = lane >> 2;          // 0..7
    int qc = (lane & 3) * 2;      // col pair within n8 tile
    float acc[4][4];
    uint32_t ah_base = (uint32_t)__cvta_generic_to_shared(ah_);
    uint32_t al_base = (uint32_t)__cvta_generic_to_shared(al_);
    uint32_t wh_base = (uint32_t)__cvta_generic_to_shared(wh_);
    uint32_t wl_base = (uint32_t)__cvta_generic_to_shared(wl_);

    int a_row  = mw * 16 + (lane & 15);
    int a_koff = (lane >> 4) * 8;
    int b_krow = (lane & 7) + ((lane >> 3) & 1) * 8;
    int b_ncol = nw * 32 + ((lane >> 4) & 1) * 8;

    // ---- GEMM 1 (3-term split) ----
    #pragma unroll
    for (int t = 0; t < 4; t++) {
        float bx = b1s[nw * 32 + t * 8 + qc];
        float by = b1s[nw * 32 + t * 8 + qc + 1];
        acc[t][0] = bx; acc[t][1] = by; acc[t][2] = bx; acc[t][3] = by;
    }
    #pragma unroll
    for (int k0 = 0; k0 < 64; k0 += 16) {
        uint32_t aoff = (uint32_t)((a_row * 72 + k0 + a_koff) * 2);
        uint32_t boff = (uint32_t)(((k0 + b_krow) * 72 + b_ncol) * 2);
        uint32_t ah0, ah1, ah2, ah3, al0, al1, al2, al3;
        ldmx4(ah0, ah1, ah2, ah3, ah_base + aoff);
        ldmx4(al0, al1, al2, al3, al_base + aoff);
        uint32_t bh0, bh1, bh2, bh3, bh4, bh5, bh6, bh7;
        uint32_t bl0, bl1, bl2, bl3, bl4, bl5, bl6, bl7;
        ldmx4t(bh0, bh1, bh2, bh3, wh_base + boff);
        ldmx4t(bh4, bh5, bh6, bh7, wh_base + boff + 32);
        ldmx4t(bl0, bl1, bl2, bl3, wl_base + boff);
        ldmx4t(bl4, bl5, bl6, bl7, wl_base + boff + 32);
        mma16816(acc[0][0], acc[0][1], acc[0][2], acc[0][3], ah0, ah1, ah2, ah3, bh0, bh1);
        mma16816(acc[1][0], acc[1][1], acc[1][2], acc[1][3], ah0, ah1, ah2, ah3, bh2, bh3);
        mma16816(acc[2][0], acc[2][1], acc[2][2], acc[2][3], ah0, ah1, ah2, ah3, bh4, bh5);
        mma16816(acc[3][0], acc[3][1], acc[3][2], acc[3][3], ah0, ah1, ah2, ah3, bh6, bh7);
        mma16816(acc[0][0], acc[0][1], acc[0][2], acc[0][3], ah0, ah1, ah2, ah3, bl0, bl1);
        mma16816(acc[1][0], acc[1][1], acc[1][2], acc[1][3], ah0, ah1, ah2, ah3, bl2, bl3);
        mma16816(acc[2][0], acc[2][1], acc[2][2], acc[2][3], ah0, ah1, ah2, ah3, bl4, bl5);
        mma16816(acc[3][0], acc[3][1], acc[3][2], acc[3][3], ah0, ah1, ah2, ah3, bl6, bl7);
        mma16816(acc[0][0], acc[0][1], acc[0][2], acc[0][3], al0, al1, al2, al3, bh0, bh1);
        mma16816(acc[1][0], acc[1][1], acc[1][2], acc[1][3], al0, al1, al2, al3, bh2, bh3);
        mma16816(acc[2][0], acc[2][1], acc[2][2], acc[2][3], al0, al1, al2, al3, bh4, bh5);
        mma16816(acc[3][0], acc[3][1], acc[3][2], acc[3][3], al0, al1, al2, al3, bh6, bh7);
    }
    __syncthreads();   // all GEMM1 reads of ah/al/wh/wl done

    // ReLU + split write back to ah/al; stash W2 -> wh/wl
    #pragma unroll
    for (int t = 0; t < 4; t++) {
        int c0 = nw * 32 + t * 8 + qc;
        float r0 = fmaxf(acc[t][0], 0.f), r1 = fmaxf(acc[t][1], 0.f);
        float r2 = fmaxf(acc[t][2], 0.f), r3 = fmaxf(acc[t][3], 0.f);
        __half h0, l0, h1, l1;
        split_h(r0, h0, l0); split_h(r1, h1, l1);
        *(__half2*)&ah_[(mw * 16 + row) * 72 + c0] = __halves2half2(h0, h1);
        *(__half2*)&al_[(mw * 16 + row) * 72 + c0] = __halves2half2(l0, l1);
        split_h(r2, h0, l0); split_h(r3, h1, l1);
        *(__half2*)&ah_[(mw * 16 + row + 8) * 72 + c0] = __halves2half2(h0, h1);
        *(__half2*)&al_[(mw * 16 + row + 8) * 72 + c0] = __halves2half2(l0, l1);
    }
    {
        int i0 = tid * 16;
        #pragma unroll
        for (int j = 0; j < 8; j++) {
            int i = i0 + j * 2;
            int k = i >> 6, n = i & 63;
            *(uint32_t*)&wh_[k * 72 + n] = w2h_st[j];
            *(uint32_t*)&wl_[k * 72 + n] = w2l_st[j];
        }
    }
    __syncthreads();

    // ---- GEMM 2 (3-term split) ----
    #pragma unroll
    for (int t = 0; t < 4; t++) {
        float bx = b2s[nw * 32 + t * 8 + qc];
        float by = b2s[nw * 32 + t * 8 + qc + 1];
        acc[t][0] = bx; acc[t][1] = by; acc[t][2] = bx; acc[t][3] = by;
    }
    #pragma unroll
    for (int k0 = 0; k0 < 64; k0 += 16) {
        uint32_t aoff = (uint32_t)((a_row * 72 + k0 + a_koff) * 2);
        uint32_t boff = (uint32_t)(((k0 + b_krow) * 72 + b_ncol) * 2);
        uint32_t ah0, ah1, ah2, ah3, al0, al1, al2, al3;
        ldmx4(ah0, ah1, ah2, ah3, ah_base + aoff);
        ldmx4(al0, al1, al2, al3, al_base + aoff);
        uint32_t bh0, bh1, bh2, bh3, bh4, bh5, bh6, bh7;
        uint32_t bl0, bl1, bl2, bl3, bl4, bl5, bl6, bl7;
        ldmx4t(bh0, bh1, bh2, bh3, wh_base + boff);
        ldmx4t(bh4, bh5, bh6, bh7, wh_base + boff + 32);
        ldmx4t(bl0, bl1, bl2, bl3, wl_base + boff);
        ldmx4t(bl4, bl5, bl6, bl7, wl_base + boff + 32);
        mma16816(acc[0][0], acc[0][1], acc[0][2], acc[0][3], ah0, ah1, ah2, ah3, bh0, bh1);
        mma16816(acc[1][0], acc[1][1], acc[1][2], acc[1][3], ah0, ah1, ah2, ah3, bh2, bh3);
        mma16816(acc[2][0], acc[2][1], acc[2][2], acc[2][3], ah0, ah1, ah2, ah3, bh4, bh5);
        mma16816(acc[3][0], acc[3][1], acc[3][2], acc[3][3], ah0, ah1, ah2, ah3, bh6, bh7);
        mma16816(acc[0][0], acc[0][1], acc[0][2], acc[0][3], ah0, ah1, ah2, ah3, bl0, bl1);
        mma16816(acc[1][0], acc[1][1], acc[1][2], acc[1][3], ah0, ah1, ah2, ah3, bl2, bl3);
        mma16816(acc[2][0], acc[2][1], acc[2][2], acc[2][3], ah0, ah1, ah2, ah3, bl4, bl5);
        mma16816(acc[3][0], acc[3][1], acc[3][2], acc[3][3], ah0, ah1, ah2, ah3, bl6, bl7);
        mma16816(acc[0][0], acc[0][1], acc[0][2], acc[0][3], al0, al1, al2, al3, bh0, bh1);
        mma16816(acc[1][0], acc[1][1], acc[1][2], acc[1][3], al0, al1, al2, al3, bh2, bh3);
        mma16816(acc[2][0], acc[2][1], acc[2][2], acc[2][3], al0, al1, al2, al3, bh4, bh5);
        mma16816(acc[3][0], acc[3][1], acc[3][2], acc[3][3], al0, al1, al2, al3, bh6, bh7);
    }
    __syncthreads();   // GEMM2 reads of u_area done before o_f overwrite

    // ---- epilogue: fp32 out to gmem + smem tile for stats ----
    {
        int r1 = mw * 16 + row;
        int node1 = n0 + r1;
        #pragma unroll
        for (int t = 0; t < 4; t++) {
            int c0 = nw * 32 + t * 8 + qc;
            o_f[r1 * 65 + c0]           = acc[t][0];
            o_f[r1 * 65 + c0 + 1]       = acc[t][1];
            o_f[(r1 + 8) * 65 + c0]     = acc[t][2];
            o_f[(r1 + 8) * 65 + c0 + 1] = acc[t][3];
            if (node1 < NN)
                *(float2*)&g_bufA[node1 * HH + c0] = make_float2(acc[t][0], acc[t][1]);
            if (node1 + 8 < NN)
                *(float2*)&g_bufA[(node1 + 8) * HH + c0] = make_float2(acc[t][2], acc[t][3]);
        }
    }
    __syncthreads();

    // ---- GraphNorm stats (block reduce per graph -> global atomics) ----
    int lastn = min(n0 + 63, NN - 1);
    int gfirst = batch[n0], glast = batch[lastn];
    int c = tid & 63, sub = tid >> 6;
    for (int g = gfirst; g <= glast; g++) {
        int lo = max(n0, g_gstart[g]);
        int hi = min(min(n0 + 64, NN), g_gstart[g + 1]);
        float s = 0.f, q = 0.f;
        for (int n = lo + sub; n < hi; n += 4) {
            float vv = o_f[(n - n0) * 65 + c];
            s += vv; q += vv * vv;
        }
        rs_[tid] = s; rq_[tid] = q;
        __syncthreads();
        if (tid < 64) {
            float ts2 = rs_[tid] + rs_[tid + 64] + rs_[tid + 128] + rs_[tid + 192];
            float tq2 = rq_[tid] + rq_[tid + 64] + rq_[tid + 128] + rq_[tid + 192];
            atomicAdd(&g_ssum[g * HH + tid], ts2);
            atomicAdd(&g_ssq[g * HH + tid], tq2);
        }
        __syncthreads();
    }
}

// ---------------- GraphNorm precompute (+ zero stats for next layer) ----------------
__global__ void k_nprep(const float* __restrict__ gw, const float* __restrict__ gb,
                        const float* __restrict__ gms) {
    int idx = blockIdx.x * blockDim.x + threadIdx.x;
    if (idx >= BB * HH) return;
    int b = idx >> 6, c = idx & 63;
    float cnt = fmaxf((float)(g_gstart[b + 1] - g_gstart[b]), 1.f);
    float mean = g_ssum[idx] / cnt;
    float ex2 = g_ssq[idx] / cnt;
    float ms = gms[c];
    float var = ex2 - (2.f * ms - ms * ms) * mean * mean;
    float sc = rsqrtf(var + GN_EPS) * gw[c];
    g_scale[idx] = sc;
    g_shift[idx] = gb[c] - ms * mean * sc;
    g_ssum[idx] = 0.f;
    g_ssq[idx] = 0.f;
}

// ---------------- GraphNorm apply + ReLU + residual (layers 1,2) ----------------
__global__ void k_apply(const int* __restrict__ batch, int accum) {
    int i4 = blockIdx.x * blockDim.x + threadIdx.x;
    if (i4 >= NN * (HH / 4)) return;
    int node = i4 >> 4;
    int c0 = (i4 & 15) * 4;
    int g = batch[node];
    const float4 v = *(const float4*)&g_bufA[i4 * 4];
    const float4 sc = *(const float4*)&g_scale[g * HH + c0];
    const float4 sh = *(const float4*)&g_shift[g * HH + c0];
    float4 o;
    o.x = fmaxf(v.x * sc.x + sh.x, 0.f);
    o.y = fmaxf(v.y * sc.y + sh.y, 0.f);
    o.z = fmaxf(v.z * sc.z + sh.z, 0.f);
    o.w = fmaxf(v.w * sc.w + sh.w, 0.f);
    *(float4*)&g_hcur[i4 * 4] = o;
    if (accum) {
        float4 hs = *(const float4*)&g_hsum[i4 * 4];
        hs.x += o.x; hs.y += o.y; hs.z += o.z; hs.w += o.w;
        *(float4*)&g_hsum[i4 * 4] = hs;
    } else {
        *(float4*)&g_hsum[i4 * 4] = o;
    }
}

// ---------------- layer-3 apply: norm + ReLU + residual + gate logits ----------------
__global__ void k_apply_gate(const int* __restrict__ batch,
                             const float* __restrict__ gw, const float* __restrict__ gb) {
    int t = blockIdx.x * blockDim.x + threadIdx.x;
    if (t >= NN * 16) return;
    int node = t >> 4;
    int c0 = (t & 15) * 4;
    int g = batch[node];
    const float4 v = *(const float4*)&g_bufA[t * 4];
    const float4 sc = *(const float4*)&g_scale[g * HH + c0];
    const float4 sh = *(const float4*)&g_shift[g * HH + c0];
    float4 o;
    o.x = fmaxf(v.x * sc.x + sh.x, 0.f);
    o.y = fmaxf(v.y * sc.y + sh.y, 0.f);
    o.z = fmaxf(v.z * sc.z + sh.z, 0.f);
    o.w = fmaxf(v.w * sc.w + sh.w, 0.f);
    float4 hs = *(const float4*)&g_hsum[t * 4];
    hs.x += o.x; hs.y += o.y; hs.z += o.z; hs.w += o.w;
    *(float4*)&g_hsum[t * 4] = hs;
    const float4 w = *(const float4*)&gw[c0];
    float d = hs.x * w.x + hs.y * w.y + hs.z * w.z + hs.w * w.w;
    d += __shfl_down_sync(0xffffffffu, d, 8, 16);
    d += __shfl_down_sync(0xffffffffu, d, 4, 16);
    d += __shfl_down_sync(0xffffffffu, d, 2, 16);
    d += __shfl_down_sync(0xffffffffu, d, 1, 16);
    if ((t & 15) == 0) g_gate[node] = d + gb[0];
}

// ---------------- fused pooling + head MLP ----------------
__global__ void k_pool_head(const float* __restrict__ u,
                            const float* __restrict__ hw1, const float* __restrict__ hb1,
                            const float* __restrict__ hw2, const float* __restrict__ hb2,
                            float* __restrict__ out) {
    int b = blockIdx.x;
    int s = g_gstart[b], e = g_gstart[b + 1];
    int tid = threadIdx.x;
    __shared__ float red[256], red2[256], red3[256];
    __shared__ float za[64], zm[64], zx[64], rr[64];
    __shared__ float sM, sD;

    // pass A: max gate
    float m = -INFINITY;
    for (int n = s + tid; n < e; n += 256) m = fmaxf(m, g_gate[n]);
    red[tid] = m;
    __syncthreads();
    for (int o = 128; o > 0; o >>= 1) {
        if (tid < o) red[tid] = fmaxf(red[tid], red[tid + o]);
        __syncthreads();
    }
    if (tid == 0) sM = red[0];
    __syncthreads();
    float mm = sM;

    // pass B: sum exp
    float d = 0.f;
    for (int n = s + tid; n < e; n += 256) d += __expf(g_gate[n] - mm);
    __syncthreads();
    red[tid] = d;
    __syncthreads();
    for (int o = 128; o > 0; o >>= 1) {
        if (tid < o) red[tid] += red[tid + o];
        __syncthreads();
    }
    if (tid == 0) sD = red[0];
    __syncthreads();
    float den = sD;

    // pass C: att / mean / max
    int c = tid & 63, l = tid >> 6;
    float fa = 0.f, fm = 0.f, fx = -INFINITY;
    for (int n = s + l; n < e; n += 4) {
        float hv = g_hsum[n * HH + c];
        float w = __expf(g_gate[n] - mm);
        fa += w * hv; fm += hv; fx = fmaxf(fx, hv);
    }
    __syncthreads();
    red[tid] = fa; red2[tid] = fm; red3[tid] = fx;
    __syncthreads();
    if (tid < 64) {
        float ta = red[tid] + red[tid + 64] + red[tid + 128] + red[tid + 192];
        float tm = red2[tid] + red2[tid + 64] + red2[tid + 128] + red2[tid + 192];
        float tx = fmaxf(fmaxf(red3[tid], red3[tid + 64]), fmaxf(red3[tid + 128], red3[tid + 192]));
        float cnt = fmaxf((float)(e - s), 1.f);
        za[tid] = (e > s) ? (ta / den) : 0.f;
        zm[tid] = tm / cnt;
        zx[tid] = tx;
    }
    __syncthreads();

    if (tid < 64) {
        float a = hb1[tid];
        #pragma unroll 4
        for (int k = 0; k < HH; k++) a += za[k] * hw1[k * HH + tid];
        #pragma unroll 4
        for (int k = 0; k < HH; k++) a += zm[k] * hw1[(HH + k) * HH + tid];
        #pragma unroll 4
        for (int k = 0; k < HH; k++) a += zx[k] * hw1[(2 * HH + k) * HH + tid];
        #pragma unroll
        for (int k = 0; k < 3; k++) a += u[b * 3 + k] * hw1[(3 * HH + k) * HH + tid];
        rr[tid] = fmaxf(a, 0.f) * hw2[tid];
    }
    __syncthreads();
    if (tid == 0) {
        float t = 0.f;
        for (int k = 0; k < 64; k++) t += rr[k];
        out[b] = t + hb2[0];
    }
}

// ---------------- launch ----------------
extern "C" void kernel_launch(void* const* d_in, const int* in_sizes, int n_in,
                              void* d_out, int out_size) {
    const float* x = (const float*)d_in[0];
    const int* ei = (const int*)d_in[1];
    const int* batch = (const int*)d_in[2];
    const float* u = (const float*)d_in[3];
    const float *wA[3], *bA[3], *wB[3], *bB[3], *gnw[3], *gnb[3], *gnms[3];
    int p = 4;
    for (int l = 0; l < 3; l++) {
        wA[l] = (const float*)d_in[p++]; bA[l] = (const float*)d_in[p++];
        wB[l] = (const float*)d_in[p++]; bB[l] = (const float*)d_in[p++];
        gnw[l] = (const float*)d_in[p++]; gnb[l] = (const float*)d_in[p++];
        gnms[l] = (const float*)d_in[p++];
    }
    const float* gate_w = (const float*)d_in[p++];
    const float* gate_b = (const float*)d_in[p++];
    const float* hw1 = (const float*)d_in[p++];
    const float* hb1 = (const float*)d_in[p++];
    const float* hw2 = (const float*)d_in[p++];
    const float* hb2 = (const float*)d_in[p++];
    float* out = (float*)d_out;

    // CSR build
    k_zero<<<(NN + 255) / 256, 256>>>();
    k_hist<<<(EE + 255) / 256, 256>>>(ei);
    k_scan1<<<SCAN_NBLK, 1024>>>();
    k_scan2<<<1, 128>>>();
    k_scan3<<<(NN + 255) / 256, 256>>>(batch);
    k_fill<<<(EE + 255) / 256, 256>>>(ei);

    // trunk: 3x (fused agg + split-fp16 HMMA MLP + stats -> nprep -> apply)
    for (int l = 0; l < 3; l++) {
        k_layer<<<(NN + 63) / 64, 256>>>(x, l == 0 ? 1 : 0, wA[l], bA[l], wB[l], bB[l], batch);
        k_nprep<<<(BB * HH + 255) / 256, 256>>>(gnw[l], gnb[l], gnms[l]);
        if (l < 2)
            k_apply<<<(NN * 16) / 256, 256>>>(batch, l == 0 ? 0 : 1);
        else
            k_apply_gate<<<(NN * 16) / 256, 256>>>(batch, gate_w, gate_b);
    }

    // fused pooling + head
    k_pool_head<<<BB, 256>>>(u, hw1, hb1, hw2, hb2, out);
    (void)in_sizes; (void)n_in; (void)out_size;
}

// round 13
// speedup vs baseline: 2.9944x; 1.1357x over previous
#include <cuda_runtime.h>
#include <cuda_fp16.h>
#include <stdint.h>
#include <math.h>

#define NN 100000
#define EE 1200000
#define BB 128
#define HH 64
#define GN_EPS 1e-5f
#define SCAN_NBLK ((NN + 1023) / 1024)

// ---------------- device scratch ----------------
__device__ __align__(16) int   g_counts[NN];
__device__ __align__(16) int   g_rowptr[NN];
__device__ __align__(16) int   g_wrptr[NN];
__device__ __align__(16) int   g_col[EE];
__device__ __align__(16) int   g_blocksum[SCAN_NBLK + 1];
__device__ __align__(16) int   g_gstart[BB + 1];
__device__ __align__(16) float g_hcur[NN * HH];   // post-norm layer output (fp32)
__device__ __align__(16) float g_bufA[NN * HH];   // pre-norm MLP output (fp32)
__device__ __align__(16) float g_hsum[NN * HH];   // residual sum (fp32)
__device__ __align__(16) float g_ssum[BB * HH];
__device__ __align__(16) float g_ssq[BB * HH];
__device__ __align__(16) float g_scale[BB * HH];
__device__ __align__(16) float g_shift[BB * HH];
__device__ __align__(16) float g_gate[NN];
// pre-split weights (hi/lo fp16), layout [l][k*64+n]
__device__ __align__(16) __half g_w1h[3][HH * HH];
__device__ __align__(16) __half g_w1l[3][HH * HH];
__device__ __align__(16) __half g_w2h[3][HH * HH];
__device__ __align__(16) __half g_w2l[3][HH * HH];

// ---------------- MMA helpers ----------------
__device__ __forceinline__ void ldmx4(uint32_t& r0, uint32_t& r1, uint32_t& r2, uint32_t& r3,
                                      uint32_t addr) {
    asm volatile("ldmatrix.sync.aligned.m8n8.x4.shared.b16 {%0,%1,%2,%3}, [%4];"
                 : "=r"(r0), "=r"(r1), "=r"(r2), "=r"(r3) : "r"(addr));
}
__device__ __forceinline__ void ldmx4t(uint32_t& r0, uint32_t& r1, uint32_t& r2, uint32_t& r3,
                                       uint32_t addr) {
    asm volatile("ldmatrix.sync.aligned.m8n8.x4.trans.shared.b16 {%0,%1,%2,%3}, [%4];"
                 : "=r"(r0), "=r"(r1), "=r"(r2), "=r"(r3) : "r"(addr));
}
__device__ __forceinline__ void mma16816(float& c0, float& c1, float& c2, float& c3,
                                         uint32_t a0, uint32_t a1, uint32_t a2, uint32_t a3,
                                         uint32_t b0, uint32_t b1) {
    asm volatile("mma.sync.aligned.m16n8k16.row.col.f32.f16.f16.f32 "
                 "{%0,%1,%2,%3}, {%4,%5,%6,%7}, {%8,%9}, {%0,%1,%2,%3};"
                 : "+f"(c0), "+f"(c1), "+f"(c2), "+f"(c3)
                 : "r"(a0), "r"(a1), "r"(a2), "r"(a3), "r"(b0), "r"(b1));
}
// split float -> (hi, lo) fp16
__device__ __forceinline__ void split_h(float v, __half& hi, __half& lo) {
    hi = __float2half(v);
    lo = __float2half(v - __half2float(hi));
}

// ---------------- weight pre-split ----------------
__global__ void k_wsplit(const float* __restrict__ w1a, const float* __restrict__ w1b,
                         const float* __restrict__ w1c,
                         const float* __restrict__ w2a, const float* __restrict__ w2b,
                         const float* __restrict__ w2c) {
    int j = blockIdx.x * blockDim.x + threadIdx.x;
    if (j >= 3 * HH * HH) return;
    int l = j >> 12, i = j & (HH * HH - 1);
    const float* W1 = (l == 0) ? w1a : ((l == 1) ? w1b : w1c);
    const float* W2 = (l == 0) ? w2a : ((l == 1) ? w2b : w2c);
    __half h, lo;
    split_h(W1[i], h, lo);
    g_w1h[l][i] = h; g_w1l[l][i] = lo;
    split_h(W2[i], h, lo);
    g_w2h[l][i] = h; g_w2l[l][i] = lo;
}

// ---------------- CSR build ----------------
__global__ void k_zero() {
    int i = blockIdx.x * blockDim.x + threadIdx.x;
    if (i < NN) g_counts[i] = 0;
    if (i < BB * HH) { g_ssum[i] = 0.f; g_ssq[i] = 0.f; }
}

__global__ void k_hist(const int* __restrict__ ei) {
    int e = blockIdx.x * blockDim.x + threadIdx.x;
    if (e < EE) atomicAdd(&g_counts[ei[EE + e]], 1);
}

// warp-shuffle block scan (1024 threads, 2 syncs)
__global__ void k_scan1() {
    __shared__ int wsum[32];
    int tid = threadIdx.x;
    int i = blockIdx.x * 1024 + tid;
    int v = (i < NN) ? g_counts[i] : 0;
    int x = v;
    int lane = tid & 31;
    #pragma unroll
    for (int o = 1; o < 32; o <<= 1) {
        int t = __shfl_up_sync(0xffffffffu, x, o);
        if (lane >= o) x += t;
    }
    if (lane == 31) wsum[tid >> 5] = x;
    __syncthreads();
    if (tid < 32) {
        int w = wsum[tid];
        #pragma unroll
        for (int o = 1; o < 32; o <<= 1) {
            int t = __shfl_up_sync(0xffffffffu, w, o);
            if (tid >= o) w += t;
        }
        wsum[tid] = w;
    }
    __syncthreads();
    int base = (tid >= 32) ? wsum[(tid >> 5) - 1] : 0;
    int incl = base + x;
    if (i < NN) g_rowptr[i] = incl - v;   // exclusive within block
    if (tid == 1023) g_blocksum[blockIdx.x] = incl;
}

// scan finalize: inline scan over per-block sums + per-graph boundaries
__global__ void k_scan3(const int* __restrict__ batch) {
    __shared__ int soff[128];
    int tid = threadIdx.x;  // 256
    if (tid < 128) soff[tid] = (tid < SCAN_NBLK) ? g_blocksum[tid] : 0;
    __syncthreads();
    for (int o = 1; o < 128; o <<= 1) {
        int t = (tid < 128 && tid >= o) ? soff[tid - o] : 0;
        __syncthreads();
        if (tid < 128) soff[tid] += t;   // inclusive
        __syncthreads();
    }
    int i = blockIdx.x * 256 + tid;
    if (i >= NN) return;
    int blk = i >> 10;
    int off = blk ? soff[blk - 1] : 0;
    int v = g_rowptr[i] + off;
    g_rowptr[i] = v;
    g_wrptr[i] = v;
    int bc = batch[i];
    int bp = (i == 0) ? -1 : batch[i - 1];
    for (int g = bp + 1; g <= bc; g++) g_gstart[g] = i;
    if (i == NN - 1)
        for (int g = bc + 1; g <= BB; g++) g_gstart[g] = NN;
}

__global__ void k_fill(const int* __restrict__ ei) {
    int e = blockIdx.x * blockDim.x + threadIdx.x;
    if (e < EE) {
        int dst = ei[EE + e];
        int pos = atomicAdd(&g_wrptr[dst], 1);
        g_col[pos] = ei[e];
    }
}

// ---------------- fused layer: fp32 GIN agg -> split-fp16 HMMA MLP -> stats ----------------
// 256 threads (8 warps), 64 nodes per block. D = Ah*Wh + Ah*Wl + Al*Wh (fp32 acc)
__global__ void __launch_bounds__(256) k_layer(
        const float* __restrict__ xin, int use_x, int lidx,
        const float* __restrict__ B1, const float* __restrict__ B2,
        const int* __restrict__ batch) {
    __shared__ __align__(16) __half wh_[HH * 72];   // current weight hi (W1 then W2)
    __shared__ __align__(16) __half wl_[HH * 72];   // current weight lo
    __shared__ __align__(16) unsigned char u_area[64 * 72 * 2 * 2];  // {ah, al} / o_f union
    __shared__ float b1s[HH], b2s[HH];
    __shared__ float rs_[256], rq_[256];
    __half* ah_ = (__half*)u_area;                  // 64 x 72 hi
    __half* al_ = (__half*)(u_area + 64 * 72 * 2);  // 64 x 72 lo
    float*  o_f = (float*)u_area;                   // 64 x 65 (reused after GEMM2)

    int tid = threadIdx.x;
    int warp = tid >> 5, lane = tid & 31;
    int n0 = blockIdx.x * 64;

    // W1 (pre-split) -> smem via uint4; W2 (pre-split) -> register stash
    const __half* __restrict__ w1hp = g_w1h[lidx];
    const __half* __restrict__ w1lp = g_w1l[lidx];
    const __half* __restrict__ w2hp = g_w2h[lidx];
    const __half* __restrict__ w2lp = g_w2l[lidx];
    #pragma unroll
    for (int i0 = tid * 8; i0 < HH * HH; i0 += 2048) {
        int k = i0 >> 6, n = i0 & 63;
        *(uint4*)&wh_[k * 72 + n] = *(const uint4*)&w1hp[i0];
        *(uint4*)&wl_[k * 72 + n] = *(const uint4*)&w1lp[i0];
    }
    uint4 s2h[2], s2l[2];
    {
        int i0 = tid * 16;
        #pragma unroll
        for (int j = 0; j < 2; j++) {
            s2h[j] = *(const uint4*)&w2hp[i0 + j * 8];
            s2l[j] = *(const uint4*)&w2lp[i0 + j * 8];
        }
    }
    if (tid < HH) { b1s[tid] = B1[tid]; b2s[tid] = B2[tid]; }

    // ---- aggregation: warp per node (8 nodes/warp), fp32, split into ah/al ----
    const float2* __restrict__ inp = use_x ? (const float2*)xin : (const float2*)g_hcur;
    #pragma unroll
    for (int i = 0; i < 8; i++) {
        int node = n0 + warp * 8 + i;
        int r = warp * 8 + i;
        float ax = 0.f, ay = 0.f;
        if (node < NN) {
            float2 f = inp[node * 32 + lane];
            ax = f.x; ay = f.y;
            int e = g_rowptr[node];
            int re = g_wrptr[node];
            for (; e + 8 <= re; e += 8) {
                int s0 = g_col[e],     s1 = g_col[e + 1], s2 = g_col[e + 2], s3 = g_col[e + 3];
                int s4 = g_col[e + 4], s5 = g_col[e + 5], s6 = g_col[e + 6], s7 = g_col[e + 7];
                float2 v0 = inp[s0 * 32 + lane];
                float2 v1 = inp[s1 * 32 + lane];
                float2 v2 = inp[s2 * 32 + lane];
                float2 v3 = inp[s3 * 32 + lane];
                float2 v4 = inp[s4 * 32 + lane];
                float2 v5 = inp[s5 * 32 + lane];
                float2 v6 = inp[s6 * 32 + lane];
                float2 v7 = inp[s7 * 32 + lane];
                ax += ((v0.x + v1.x) + (v2.x + v3.x)) + ((v4.x + v5.x) + (v6.x + v7.x));
                ay += ((v0.y + v1.y) + (v2.y + v3.y)) + ((v4.y + v5.y) + (v6.y + v7.y));
            }
            for (; e + 4 <= re; e += 4) {
                int s0 = g_col[e], s1 = g_col[e + 1], s2 = g_col[e + 2], s3 = g_col[e + 3];
                float2 v0 = inp[s0 * 32 + lane];
                float2 v1 = inp[s1 * 32 + lane];
                float2 v2 = inp[s2 * 32 + lane];
                float2 v3 = inp[s3 * 32 + lane];
                ax += (v0.x + v1.x) + (v2.x + v3.x);
                ay += (v0.y + v1.y) + (v2.y + v3.y);
            }
            for (; e < re; e++) {
                float2 v = inp[g_col[e] * 32 + lane];
                ax += v.x; ay += v.y;
            }
        }
        __half hx, lx, hy, ly;
        split_h(ax, hx, lx);
        split_h(ay, hy, ly);
        __half2 hh = __halves2half2(hx, hy), ll = __halves2half2(lx, ly);
        ((__half2*)(ah_ + r * 72))[lane] = hh;
        ((__half2*)(al_ + r * 72))[lane] = ll;
    }
    __syncthreads();

    // ---- MMA setup ----
    int mw = warp & 3;            // 16-row block
    int nw = warp >> 2;           // 32-col block
    int row = lane >> 2;          // 0..7
    int qc = (lane & 3) * 2;      // col pair within n8 tile
    float acc[4][4];
    uint32_t ah_base = (uint32_t)__cvta_generic_to_shared(ah_);
    uint32_t al_base = (uint32_t)__cvta_generic_to_shared(al_);
    uint32_t wh_base = (uint32_t)__cvta_generic_to_shared(wh_);
    uint32_t wl_base = (uint32_t)__cvta_generic_to_shared(wl_);

    int a_row  = mw * 16 + (lane & 15);
    int a_koff = (lane >> 4) * 8;
    int b_krow = (lane & 7) + ((lane >> 3) & 1) * 8;
    int b_ncol = nw * 32 + ((lane >> 4) & 1) * 8;

    // ---- GEMM 1 (3-term split) ----
    #pragma unroll
    for (int t = 0; t < 4; t++) {
        float bx = b1s[nw * 32 + t * 8 + qc];
        float by = b1s[nw * 32 + t * 8 + qc + 1];
        acc[t][0] = bx; acc[t][1] = by; acc[t][2] = bx; acc[t][3] = by;
    }
    #pragma unroll
    for (int k0 = 0; k0 < 64; k0 += 16) {
        uint32_t aoff = (uint32_t)((a_row * 72 + k0 + a_koff) * 2);
        uint32_t boff = (uint32_t)(((k0 + b_krow) * 72 + b_ncol) * 2);
        uint32_t ah0, ah1, ah2, ah3, al0, al1, al2, al3;
        ldmx4(ah0, ah1, ah2, ah3, ah_base + aoff);
        ldmx4(al0, al1, al2, al3, al_base + aoff);
        uint32_t bh0, bh1, bh2, bh3, bh4, bh5, bh6, bh7;
        uint32_t bl0, bl1, bl2, bl3, bl4, bl5, bl6, bl7;
        ldmx4t(bh0, bh1, bh2, bh3, wh_base + boff);
        ldmx4t(bh4, bh5, bh6, bh7, wh_base + boff + 32);
        ldmx4t(bl0, bl1, bl2, bl3, wl_base + boff);
        ldmx4t(bl4, bl5, bl6, bl7, wl_base + boff + 32);
        mma16816(acc[0][0], acc[0][1], acc[0][2], acc[0][3], ah0, ah1, ah2, ah3, bh0, bh1);
        mma16816(acc[1][0], acc[1][1], acc[1][2], acc[1][3], ah0, ah1, ah2, ah3, bh2, bh3);
        mma16816(acc[2][0], acc[2][1], acc[2][2], acc[2][3], ah0, ah1, ah2, ah3, bh4, bh5);
        mma16816(acc[3][0], acc[3][1], acc[3][2], acc[3][3], ah0, ah1, ah2, ah3, bh6, bh7);
        mma16816(acc[0][0], acc[0][1], acc[0][2], acc[0][3], ah0, ah1, ah2, ah3, bl0, bl1);
        mma16816(acc[1][0], acc[1][1], acc[1][2], acc[1][3], ah0, ah1, ah2, ah3, bl2, bl3);
        mma16816(acc[2][0], acc[2][1], acc[2][2], acc[2][3], ah0, ah1, ah2, ah3, bl4, bl5);
        mma16816(acc[3][0], acc[3][1], acc[3][2], acc[3][3], ah0, ah1, ah2, ah3, bl6, bl7);
        mma16816(acc[0][0], acc[0][1], acc[0][2], acc[0][3], al0, al1, al2, al3, bh0, bh1);
        mma16816(acc[1][0], acc[1][1], acc[1][2], acc[1][3], al0, al1, al2, al3, bh2, bh3);
        mma16816(acc[2][0], acc[2][1], acc[2][2], acc[2][3], al0, al1, al2, al3, bh4, bh5);
        mma16816(acc[3][0], acc[3][1], acc[3][2], acc[3][3], al0, al1, al2, al3, bh6, bh7);
    }
    __syncthreads();   // all GEMM1 reads of ah/al/wh/wl done

    // ReLU + split write back to ah/al; stash W2 -> wh/wl
    #pragma unroll
    for (int t = 0; t < 4; t++) {
        int c0 = nw * 32 + t * 8 + qc;
        float r0 = fmaxf(acc[t][0], 0.f), r1 = fmaxf(acc[t][1], 0.f);
        float r2 = fmaxf(acc[t][2], 0.f), r3 = fmaxf(acc[t][3], 0.f);
        __half h0, l0, h1, l1;
        split_h(r0, h0, l0); split_h(r1, h1, l1);
        *(__half2*)&ah_[(mw * 16 + row) * 72 + c0] = __halves2half2(h0, h1);
        *(__half2*)&al_[(mw * 16 + row) * 72 + c0] = __halves2half2(l0, l1);
        split_h(r2, h0, l0); split_h(r3, h1, l1);
        *(__half2*)&ah_[(mw * 16 + row + 8) * 72 + c0] = __halves2half2(h0, h1);
        *(__half2*)&al_[(mw * 16 + row + 8) * 72 + c0] = __halves2half2(l0, l1);
    }
    {
        int i0 = tid * 16;
        #pragma unroll
        for (int j = 0; j < 2; j++) {
            int idx = i0 + j * 8;
            int k = idx >> 6, n = idx & 63;
            *(uint4*)&wh_[k * 72 + n] = s2h[j];
            *(uint4*)&wl_[k * 72 + n] = s2l[j];
        }
    }
    __syncthreads();

    // ---- GEMM 2 (3-term split) ----
    #pragma unroll
    for (int t = 0; t < 4; t++) {
        float bx = b2s[nw * 32 + t * 8 + qc];
        float by = b2s[nw * 32 + t * 8 + qc + 1];
        acc[t][0] = bx; acc[t][1] = by; acc[t][2] = bx; acc[t][3] = by;
    }
    #pragma unroll
    for (int k0 = 0; k0 < 64; k0 += 16) {
        uint32_t aoff = (uint32_t)((a_row * 72 + k0 + a_koff) * 2);
        uint32_t boff = (uint32_t)(((k0 + b_krow) * 72 + b_ncol) * 2);
        uint32_t ah0, ah1, ah2, ah3, al0, al1, al2, al3;
        ldmx4(ah0, ah1, ah2, ah3, ah_base + aoff);
        ldmx4(al0, al1, al2, al3, al_base + aoff);
        uint32_t bh0, bh1, bh2, bh3, bh4, bh5, bh6, bh7;
        uint32_t bl0, bl1, bl2, bl3, bl4, bl5, bl6, bl7;
        ldmx4t(bh0, bh1, bh2, bh3, wh_base + boff);
        ldmx4t(bh4, bh5, bh6, bh7, wh_base + boff + 32);
        ldmx4t(bl0, bl1, bl2, bl3, wl_base + boff);
        ldmx4t(bl4, bl5, bl6, bl7, wl_base + boff + 32);
        mma16816(acc[0][0], acc[0][1], acc[0][2], acc[0][3], ah0, ah1, ah2, ah3, bh0, bh1);
        mma16816(acc[1][0], acc[1][1], acc[1][2], acc[1][3], ah0, ah1, ah2, ah3, bh2, bh3);
        mma16816(acc[2][0], acc[2][1], acc[2][2], acc[2][3], ah0, ah1, ah2, ah3, bh4, bh5);
        mma16816(acc[3][0], acc[3][1], acc[3][2], acc[3][3], ah0, ah1, ah2, ah3, bh6, bh7);
        mma16816(acc[0][0], acc[0][1], acc[0][2], acc[0][3], ah0, ah1, ah2, ah3, bl0, bl1);
        mma16816(acc[1][0], acc[1][1], acc[1][2], acc[1][3], ah0, ah1, ah2, ah3, bl2, bl3);
        mma16816(acc[2][0], acc[2][1], acc[2][2], acc[2][3], ah0, ah1, ah2, ah3, bl4, bl5);
        mma16816(acc[3][0], acc[3][1], acc[3][2], acc[3][3], ah0, ah1, ah2, ah3, bl6, bl7);
        mma16816(acc[0][0], acc[0][1], acc[0][2], acc[0][3], al0, al1, al2, al3, bh0, bh1);
        mma16816(acc[1][0], acc[1][1], acc[1][2], acc[1][3], al0, al1, al2, al3, bh2, bh3);
        mma16816(acc[2][0], acc[2][1], acc[2][2], acc[2][3], al0, al1, al2, al3, bh4, bh5);
        mma16816(acc[3][0], acc[3][1], acc[3][2], acc[3][3], al0, al1, al2, al3, bh6, bh7);
    }
    __syncthreads();   // GEMM2 reads of u_area done before o_f overwrite

    // ---- epilogue: fp32 out to gmem + smem tile for stats ----
    {
        int r1 = mw * 16 + row;
        int node1 = n0 + r1;
        #pragma unroll
        for (int t = 0; t < 4; t++) {
            int c0 = nw * 32 + t * 8 + qc;
            o_f[r1 * 65 + c0]           = acc[t][0];
            o_f[r1 * 65 + c0 + 1]       = acc[t][1];
            o_f[(r1 + 8) * 65 + c0]     = acc[t][2];
            o_f[(r1 + 8) * 65 + c0 + 1] = acc[t][3];
            if (node1 < NN)
                *(float2*)&g_bufA[node1 * HH + c0] = make_float2(acc[t][0], acc[t][1]);
            if (node1 + 8 < NN)
                *(float2*)&g_bufA[(node1 + 8) * HH + c0] = make_float2(acc[t][2], acc[t][3]);
        }
    }
    __syncthreads();

    // ---- GraphNorm stats (block reduce per graph -> global atomics) ----
    int lastn = min(n0 + 63, NN - 1);
    int gfirst = batch[n0], glast = batch[lastn];
    int c = tid & 63, sub = tid >> 6;
    for (int g = gfirst; g <= glast; g++) {
        int lo = max(n0, g_gstart[g]);
        int hi = min(min(n0 + 64, NN), g_gstart[g + 1]);
        float s = 0.f, q = 0.f;
        for (int n = lo + sub; n < hi; n += 4) {
            float vv = o_f[(n - n0) * 65 + c];
            s += vv; q += vv * vv;
        }
        rs_[tid] = s; rq_[tid] = q;
        __syncthreads();
        if (tid < 64) {
            float ts2 = rs_[tid] + rs_[tid + 64] + rs_[tid + 128] + rs_[tid + 192];
            float tq2 = rq_[tid] + rq_[tid + 64] + rq_[tid + 128] + rq_[tid + 192];
            atomicAdd(&g_ssum[g * HH + tid], ts2);
            atomicAdd(&g_ssq[g * HH + tid], tq2);
        }
        __syncthreads();
    }
}

// ---------------- GraphNorm precompute (+ zero stats for next layer) ----------------
__global__ void k_nprep(const float* __restrict__ gw, const float* __restrict__ gb,
                        const float* __restrict__ gms) {
    int idx = blockIdx.x * blockDim.x + threadIdx.x;
    if (idx >= BB * HH) return;
    int b = idx >> 6, c = idx & 63;
    float cnt = fmaxf((float)(g_gstart[b + 1] - g_gstart[b]), 1.f);
    float mean = g_ssum[idx] / cnt;
    float ex2 = g_ssq[idx] / cnt;
    float ms = gms[c];
    float var = ex2 - (2.f * ms - ms * ms) * mean * mean;
    float sc = rsqrtf(var + GN_EPS) * gw[c];
    g_scale[idx] = sc;
    g_shift[idx] = gb[c] - ms * mean * sc;
    g_ssum[idx] = 0.f;
    g_ssq[idx] = 0.f;
}

// ---------------- GraphNorm apply + ReLU + residual (layers 1,2) ----------------
__global__ void k_apply(const int* __restrict__ batch, int accum) {
    int i4 = blockIdx.x * blockDim.x + threadIdx.x;
    if (i4 >= NN * (HH / 4)) return;
    int node = i4 >> 4;
    int c0 = (i4 & 15) * 4;
    int g = batch[node];
    const float4 v = *(const float4*)&g_bufA[i4 * 4];
    const float4 sc = *(const float4*)&g_scale[g * HH + c0];
    const float4 sh = *(const float4*)&g_shift[g * HH + c0];
    float4 o;
    o.x = fmaxf(v.x * sc.x + sh.x, 0.f);
    o.y = fmaxf(v.y * sc.y + sh.y, 0.f);
    o.z = fmaxf(v.z * sc.z + sh.z, 0.f);
    o.w = fmaxf(v.w * sc.w + sh.w, 0.f);
    *(float4*)&g_hcur[i4 * 4] = o;
    if (accum) {
        float4 hs = *(const float4*)&g_hsum[i4 * 4];
        hs.x += o.x; hs.y += o.y; hs.z += o.z; hs.w += o.w;
        *(float4*)&g_hsum[i4 * 4] = hs;
    } else {
        *(float4*)&g_hsum[i4 * 4] = o;
    }
}

// ---------------- layer-3 apply: norm + ReLU + residual + gate logits ----------------
__global__ void k_apply_gate(const int* __restrict__ batch,
                             const float* __restrict__ gw, const float* __restrict__ gb) {
    int t = blockIdx.x * blockDim.x + threadIdx.x;
    if (t >= NN * 16) return;
    int node = t >> 4;
    int c0 = (t & 15) * 4;
    int g = batch[node];
    const float4 v = *(const float4*)&g_bufA[t * 4];
    const float4 sc = *(const float4*)&g_scale[g * HH + c0];
    const float4 sh = *(const float4*)&g_shift[g * HH + c0];
    float4 o;
    o.x = fmaxf(v.x * sc.x + sh.x, 0.f);
    o.y = fmaxf(v.y * sc.y + sh.y, 0.f);
    o.z = fmaxf(v.z * sc.z + sh.z, 0.f);
    o.w = fmaxf(v.w * sc.w + sh.w, 0.f);
    float4 hs = *(const float4*)&g_hsum[t * 4];
    hs.x += o.x; hs.y += o.y; hs.z += o.z; hs.w += o.w;
    *(float4*)&g_hsum[t * 4] = hs;
    const float4 w = *(const float4*)&gw[c0];
    float d = hs.x * w.x + hs.y * w.y + hs.z * w.z + hs.w * w.w;
    d += __shfl_down_sync(0xffffffffu, d, 8, 16);
    d += __shfl_down_sync(0xffffffffu, d, 4, 16);
    d += __shfl_down_sync(0xffffffffu, d, 2, 16);
    d += __shfl_down_sync(0xffffffffu, d, 1, 16);
    if ((t & 15) == 0) g_gate[node] = d + gb[0];
}

// ---------------- fused pooling + head MLP ----------------
__global__ void k_pool_head(const float* __restrict__ u,
                            const float* __restrict__ hw1, const float* __restrict__ hb1,
                            const float* __restrict__ hw2, const float* __restrict__ hb2,
                            float* __restrict__ out) {
    int b = blockIdx.x;
    int s = g_gstart[b], e = g_gstart[b + 1];
    int tid = threadIdx.x;
    __shared__ float red[256], red2[256], red3[256];
    __shared__ float za[64], zm[64], zx[64], rr[64];
    __shared__ float sM, sD;

    // pass A: max gate
    float m = -INFINITY;
    for (int n = s + tid; n < e; n += 256) m = fmaxf(m, g_gate[n]);
    red[tid] = m;
    __syncthreads();
    for (int o = 128; o > 0; o >>= 1) {
        if (tid < o) red[tid] = fmaxf(red[tid], red[tid + o]);
        __syncthreads();
    }
    if (tid == 0) sM = red[0];
    __syncthreads();
    float mm = sM;

    // pass B: sum exp
    float d = 0.f;
    for (int n = s + tid; n < e; n += 256) d += __expf(g_gate[n] - mm);
    __syncthreads();
    red[tid] = d;
    __syncthreads();
    for (int o = 128; o > 0; o >>= 1) {
        if (tid < o) red[tid] += red[tid + o];
        __syncthreads();
    }
    if (tid == 0) sD = red[0];
    __syncthreads();
    float den = sD;

    // pass C: att / mean / max
    int c = tid & 63, l = tid >> 6;
    float fa = 0.f, fm = 0.f, fx = -INFINITY;
    for (int n = s + l; n < e; n += 4) {
        float hv = g_hsum[n * HH + c];
        float w = __expf(g_gate[n] - mm);
        fa += w * hv; fm += hv; fx = fmaxf(fx, hv);
    }
    __syncthreads();
    red[tid] = fa; red2[tid] = fm; red3[tid] = fx;
    __syncthreads();
    if (tid < 64) {
        float ta = red[tid] + red[tid + 64] + red[tid + 128] + red[tid + 192];
        float tm = red2[tid] + red2[tid + 64] + red2[tid + 128] + red2[tid + 192];
        float tx = fmaxf(fmaxf(red3[tid], red3[tid + 64]), fmaxf(red3[tid + 128], red3[tid + 192]));
        float cnt = fmaxf((float)(e - s), 1.f);
        za[tid] = (e > s) ? (ta / den) : 0.f;
        zm[tid] = tm / cnt;
        zx[tid] = tx;
    }
    __syncthreads();

    if (tid < 64) {
        float a = hb1[tid];
        #pragma unroll 4
        for (int k = 0; k < HH; k++) a += za[k] * hw1[k * HH + tid];
        #pragma unroll 4
        for (int k = 0; k < HH; k++) a += zm[k] * hw1[(HH + k) * HH + tid];
        #pragma unroll 4
        for (int k = 0; k < HH; k++) a += zx[k] * hw1[(2 * HH + k) * HH + tid];
        #pragma unroll
        for (int k = 0; k < 3; k++) a += u[b * 3 + k] * hw1[(3 * HH + k) * HH + tid];
        rr[tid] = fmaxf(a, 0.f) * hw2[tid];
    }
    __syncthreads();
    if (tid == 0) {
        float t = 0.f;
        for (int k = 0; k < 64; k++) t += rr[k];
        out[b] = t + hb2[0];
    }
}

// ---------------- launch ----------------
extern "C" void kernel_launch(void* const* d_in, const int* in_sizes, int n_in,
                              void* d_out, int out_size) {
    const float* x = (const float*)d_in[0];
    const int* ei = (const int*)d_in[1];
    const int* batch = (const int*)d_in[2];
    const float* u = (const float*)d_in[3];
    const float *wA[3], *bA[3], *wB[3], *bB[3], *gnw[3], *gnb[3], *gnms[3];
    int p = 4;
    for (int l = 0; l < 3; l++) {
        wA[l] = (const float*)d_in[p++]; bA[l] = (const float*)d_in[p++];
        wB[l] = (const float*)d_in[p++]; bB[l] = (const float*)d_in[p++];
        gnw[l] = (const float*)d_in[p++]; gnb[l] = (const float*)d_in[p++];
        gnms[l] = (const float*)d_in[p++];
    }
    const float* gate_w = (const float*)d_in[p++];
    const float* gate_b = (const float*)d_in[p++];
    const float* hw1 = (const float*)d_in[p++];
    const float* hb1 = (const float*)d_in[p++];
    const float* hw2 = (const float*)d_in[p++];
    const float* hb2 = (const float*)d_in[p++];
    float* out = (float*)d_out;

    // CSR build + weight pre-split
    k_wsplit<<<(3 * HH * HH + 255) / 256, 256>>>(wA[0], wA[1], wA[2], wB[0], wB[1], wB[2]);
    k_zero<<<(NN + 255) / 256, 256>>>();
    k_hist<<<(EE + 255) / 256, 256>>>(ei);
    k_scan1<<<SCAN_NBLK, 1024>>>();
    k_scan3<<<(NN + 255) / 256, 256>>>(batch);
    k_fill<<<(EE + 255) / 256, 256>>>(ei);

    // trunk: 3x (fused agg + split-fp16 HMMA MLP + stats -> nprep -> apply)
    for (int l = 0; l < 3; l++) {
        k_layer<<<(NN + 63) / 64, 256>>>(x, l == 0 ? 1 : 0, l, bA[l], bB[l], batch);
        k_nprep<<<(BB * HH + 255) / 256, 256>>>(gnw[l], gnb[l], gnms[l]);
        if (l < 2)
            k_apply<<<(NN * 16) / 256, 256>>>(batch, l == 0 ? 0 : 1);
        else
            k_apply_gate<<<(NN * 16) / 256, 256>>>(batch, gate_w, gate_b);
    }

    // fused pooling + head
    k_pool_head<<<BB, 256>>>(u, hw1, hb1, hw2, hb2, out);
    (void)in_sizes; (void)n_in; (void)out_size;
}

// round 14
// speedup vs baseline: 3.0684x; 1.0247x over previous
#include <cuda_runtime.h>
#include <cuda_fp16.h>
#include <stdint.h>
#include <math.h>

#define NN 100000
#define EE 1200000
#define BB 128
#define HH 64
#define GN_EPS 1e-5f
#define SCAN_NBLK ((NN + 1023) / 1024)

// ---------------- device scratch ----------------
__device__ __align__(16) int   g_counts[NN];
__device__ __align__(16) int   g_rowptr[NN];
__device__ __align__(16) int   g_wrptr[NN];
__device__ __align__(16) int   g_col[EE];
__device__ __align__(16) int   g_blocksum[SCAN_NBLK + 1];
__device__ __align__(16) int   g_gstart[BB + 1];
__device__ __align__(16) float g_hcur[NN * HH];   // post-norm layer output (fp32)
__device__ __align__(16) float g_bufA[NN * HH];   // pre-norm MLP output (fp32)
__device__ __align__(16) float g_hsum[NN * HH];   // residual sum (fp32)
__device__ __align__(16) float g_ssum3[3][BB * HH];
__device__ __align__(16) float g_ssq3[3][BB * HH];
__device__ __align__(16) float g_gate[NN];
// pre-split weights (hi/lo fp16), layout [l][k*64+n]
__device__ __align__(16) __half g_w1h[3][HH * HH];
__device__ __align__(16) __half g_w1l[3][HH * HH];
__device__ __align__(16) __half g_w2h[3][HH * HH];
__device__ __align__(16) __half g_w2l[3][HH * HH];

// ---------------- MMA helpers ----------------
__device__ __forceinline__ void ldmx4(uint32_t& r0, uint32_t& r1, uint32_t& r2, uint32_t& r3,
                                      uint32_t addr) {
    asm volatile("ldmatrix.sync.aligned.m8n8.x4.shared.b16 {%0,%1,%2,%3}, [%4];"
                 : "=r"(r0), "=r"(r1), "=r"(r2), "=r"(r3) : "r"(addr));
}
__device__ __forceinline__ void ldmx4t(uint32_t& r0, uint32_t& r1, uint32_t& r2, uint32_t& r3,
                                       uint32_t addr) {
    asm volatile("ldmatrix.sync.aligned.m8n8.x4.trans.shared.b16 {%0,%1,%2,%3}, [%4];"
                 : "=r"(r0), "=r"(r1), "=r"(r2), "=r"(r3) : "r"(addr));
}
__device__ __forceinline__ void mma16816(float& c0, float& c1, float& c2, float& c3,
                                         uint32_t a0, uint32_t a1, uint32_t a2, uint32_t a3,
                                         uint32_t b0, uint32_t b1) {
    asm volatile("mma.sync.aligned.m16n8k16.row.col.f32.f16.f16.f32 "
                 "{%0,%1,%2,%3}, {%4,%5,%6,%7}, {%8,%9}, {%0,%1,%2,%3};"
                 : "+f"(c0), "+f"(c1), "+f"(c2), "+f"(c3)
                 : "r"(a0), "r"(a1), "r"(a2), "r"(a3), "r"(b0), "r"(b1));
}
// split float -> (hi, lo) fp16
__device__ __forceinline__ void split_h(float v, __half& hi, __half& lo) {
    hi = __float2half(v);
    lo = __float2half(v - __half2float(hi));
}

// ---------------- init: zero counts + stats, pre-split weights ----------------
__global__ void k_init(const float* __restrict__ w1a, const float* __restrict__ w1b,
                       const float* __restrict__ w1c,
                       const float* __restrict__ w2a, const float* __restrict__ w2b,
                       const float* __restrict__ w2c) {
    int i = blockIdx.x * blockDim.x + threadIdx.x;
    if (i < NN) g_counts[i] = 0;
    if (i < 3 * BB * HH) {
        ((float*)g_ssum3)[i] = 0.f;
        ((float*)g_ssq3)[i] = 0.f;
    }
    if (i < 3 * HH * HH) {
        int l = i >> 12, j = i & (HH * HH - 1);
        const float* W1 = (l == 0) ? w1a : ((l == 1) ? w1b : w1c);
        const float* W2 = (l == 0) ? w2a : ((l == 1) ? w2b : w2c);
        __half h, lo;
        split_h(W1[j], h, lo);
        g_w1h[l][j] = h; g_w1l[l][j] = lo;
        split_h(W2[j], h, lo);
        g_w2h[l][j] = h; g_w2l[l][j] = lo;
    }
}

// ---------------- CSR build ----------------
__global__ void k_hist(const int* __restrict__ ei) {
    int e = blockIdx.x * blockDim.x + threadIdx.x;
    if (e < EE) atomicAdd(&g_counts[ei[EE + e]], 1);
}

// warp-shuffle block scan (1024 threads, 2 syncs)
__global__ void k_scan1() {
    __shared__ int wsum[32];
    int tid = threadIdx.x;
    int i = blockIdx.x * 1024 + tid;
    int v = (i < NN) ? g_counts[i] : 0;
    int x = v;
    int lane = tid & 31;
    #pragma unroll
    for (int o = 1; o < 32; o <<= 1) {
        int t = __shfl_up_sync(0xffffffffu, x, o);
        if (lane >= o) x += t;
    }
    if (lane == 31) wsum[tid >> 5] = x;
    __syncthreads();
    if (tid < 32) {
        int w = wsum[tid];
        #pragma unroll
        for (int o = 1; o < 32; o <<= 1) {
            int t = __shfl_up_sync(0xffffffffu, w, o);
            if (tid >= o) w += t;
        }
        wsum[tid] = w;
    }
    __syncthreads();
    int base = (tid >= 32) ? wsum[(tid >> 5) - 1] : 0;
    int incl = base + x;
    if (i < NN) g_rowptr[i] = incl - v;   // exclusive within block
    if (tid == 1023) g_blocksum[blockIdx.x] = incl;
}

// scan finalize: inline scan over per-block sums + per-graph boundaries
__global__ void k_scan3(const int* __restrict__ batch) {
    __shared__ int soff[128];
    int tid = threadIdx.x;  // 256
    if (tid < 128) soff[tid] = (tid < SCAN_NBLK) ? g_blocksum[tid] : 0;
    __syncthreads();
    for (int o = 1; o < 128; o <<= 1) {
        int t = (tid < 128 && tid >= o) ? soff[tid - o] : 0;
        __syncthreads();
        if (tid < 128) soff[tid] += t;   // inclusive
        __syncthreads();
    }
    int i = blockIdx.x * 256 + tid;
    if (i >= NN) return;
    int blk = i >> 10;
    int off = blk ? soff[blk - 1] : 0;
    int v = g_rowptr[i] + off;
    g_rowptr[i] = v;
    g_wrptr[i] = v;
    int bc = batch[i];
    int bp = (i == 0) ? -1 : batch[i - 1];
    for (int g = bp + 1; g <= bc; g++) g_gstart[g] = i;
    if (i == NN - 1)
        for (int g = bc + 1; g <= BB; g++) g_gstart[g] = NN;
}

__global__ void k_fill(const int* __restrict__ ei) {
    int e = blockIdx.x * blockDim.x + threadIdx.x;
    if (e < EE) {
        int dst = ei[EE + e];
        int pos = atomicAdd(&g_wrptr[dst], 1);
        g_col[pos] = ei[e];
    }
}

// ---------------- fused layer: fp32 GIN agg -> split-fp16 HMMA MLP -> stats ----------------
// 256 threads (8 warps), 64 nodes per block. D = Ah*Wh + Ah*Wl + Al*Wh (fp32 acc)
__global__ void __launch_bounds__(256) k_layer(
        const float* __restrict__ xin, int use_x, int lidx,
        const float* __restrict__ B1, const float* __restrict__ B2,
        const int* __restrict__ batch) {
    __shared__ __align__(16) __half wh_[HH * 72];   // current weight hi (W1 then W2)
    __shared__ __align__(16) __half wl_[HH * 72];   // current weight lo
    __shared__ __align__(16) unsigned char u_area[64 * 72 * 2 * 2];  // {ah, al} / o_f union
    __shared__ float b1s[HH], b2s[HH];
    __shared__ float rs_[256], rq_[256];
    __half* ah_ = (__half*)u_area;                  // 64 x 72 hi
    __half* al_ = (__half*)(u_area + 64 * 72 * 2);  // 64 x 72 lo
    float*  o_f = (float*)u_area;                   // 64 x 65 (reused after GEMM2)

    int tid = threadIdx.x;
    int warp = tid >> 5, lane = tid & 31;
    int n0 = blockIdx.x * 64;

    // W1 (pre-split) -> smem via uint4; W2 (pre-split) -> register stash
    const __half* __restrict__ w1hp = g_w1h[lidx];
    const __half* __restrict__ w1lp = g_w1l[lidx];
    const __half* __restrict__ w2hp = g_w2h[lidx];
    const __half* __restrict__ w2lp = g_w2l[lidx];
    #pragma unroll
    for (int i0 = tid * 8; i0 < HH * HH; i0 += 2048) {
        int k = i0 >> 6, n = i0 & 63;
        *(uint4*)&wh_[k * 72 + n] = *(const uint4*)&w1hp[i0];
        *(uint4*)&wl_[k * 72 + n] = *(const uint4*)&w1lp[i0];
    }
    uint4 s2h[2], s2l[2];
    {
        int i0 = tid * 16;
        #pragma unroll
        for (int j = 0; j < 2; j++) {
            s2h[j] = *(const uint4*)&w2hp[i0 + j * 8];
            s2l[j] = *(const uint4*)&w2lp[i0 + j * 8];
        }
    }
    if (tid < HH) { b1s[tid] = B1[tid]; b2s[tid] = B2[tid]; }

    // ---- aggregation: warp per node (8 nodes/warp), fp32, split into ah/al ----
    // main unroll-8 + ONE predicated 8-wide tail (dup-index slots hit L1, masked to 0)
    const float2* __restrict__ inp = use_x ? (const float2*)xin : (const float2*)g_hcur;
    #pragma unroll
    for (int i = 0; i < 8; i++) {
        int node = n0 + warp * 8 + i;
        int r = warp * 8 + i;
        float ax = 0.f, ay = 0.f;
        if (node < NN) {
            float2 f = inp[node * 32 + lane];
            ax = f.x; ay = f.y;
            int e = g_rowptr[node];
            int re = g_wrptr[node];
            for (; e + 8 <= re; e += 8) {
                int s0 = g_col[e],     s1 = g_col[e + 1], s2 = g_col[e + 2], s3 = g_col[e + 3];
                int s4 = g_col[e + 4], s5 = g_col[e + 5], s6 = g_col[e + 6], s7 = g_col[e + 7];
                float2 v0 = inp[s0 * 32 + lane];
                float2 v1 = inp[s1 * 32 + lane];
                float2 v2 = inp[s2 * 32 + lane];
                float2 v3 = inp[s3 * 32 + lane];
                float2 v4 = inp[s4 * 32 + lane];
                float2 v5 = inp[s5 * 32 + lane];
                float2 v6 = inp[s6 * 32 + lane];
                float2 v7 = inp[s7 * 32 + lane];
                ax += ((v0.x + v1.x) + (v2.x + v3.x)) + ((v4.x + v5.x) + (v6.x + v7.x));
                ay += ((v0.y + v1.y) + (v2.y + v3.y)) + ((v4.y + v5.y) + (v6.y + v7.y));
            }
            int rem = re - e;
            if (rem > 0) {
                #pragma unroll
                for (int j = 0; j < 7; j++) {
                    int idx = g_col[e + ((j < rem) ? j : 0)];
                    float2 v = inp[idx * 32 + lane];
                    float msk = (j < rem) ? 1.f : 0.f;
                    ax += v.x * msk; ay += v.y * msk;
                }
            }
        }
        __half hx, lx, hy, ly;
        split_h(ax, hx, lx);
        split_h(ay, hy, ly);
        __half2 hh = __halves2half2(hx, hy), ll = __halves2half2(lx, ly);
        ((__half2*)(ah_ + r * 72))[lane] = hh;
        ((__half2*)(al_ + r * 72))[lane] = ll;
    }
    __syncthreads();

    // ---- MMA setup ----
    int mw = warp & 3;            // 16-row block
    int nw = warp >> 2;           // 32-col block
    int row = lane >> 2;          // 0..7
    int qc = (lane & 3) * 2;      // col pair within n8 tile
    float acc[4][4];
    uint32_t ah_base = (uint32_t)__cvta_generic_to_shared(ah_);
    uint32_t al_base = (uint32_t)__cvta_generic_to_shared(al_);
    uint32_t wh_base = (uint32_t)__cvta_generic_to_shared(wh_);
    uint32_t wl_base = (uint32_t)__cvta_generic_to_shared(wl_);

    int a_row  = mw * 16 + (lane & 15);
    int a_koff = (lane >> 4) * 8;
    int b_krow = (lane & 7) + ((lane >> 3) & 1) * 8;
    int b_ncol = nw * 32 + ((lane >> 4) & 1) * 8;

    // ---- GEMM 1 (3-term split) ----
    #pragma unroll
    for (int t = 0; t < 4; t++) {
        float bx = b1s[nw * 32 + t * 8 + qc];
        float by = b1s[nw * 32 + t * 8 + qc + 1];
        acc[t][0] = bx; acc[t][1] = by; acc[t][2] = bx; acc[t][3] = by;
    }
    #pragma unroll
    for (int k0 = 0; k0 < 64; k0 += 16) {
        uint32_t aoff = (uint32_t)((a_row * 72 + k0 + a_koff) * 2);
        uint32_t boff = (uint32_t)(((k0 + b_krow) * 72 + b_ncol) * 2);
        uint32_t ah0, ah1, ah2, ah3, al0, al1, al2, al3;
        ldmx4(ah0, ah1, ah2, ah3, ah_base + aoff);
        ldmx4(al0, al1, al2, al3, al_base + aoff);
        uint32_t bh0, bh1, bh2, bh3, bh4, bh5, bh6, bh7;
        uint32_t bl0, bl1, bl2, bl3, bl4, bl5, bl6, bl7;
        ldmx4t(bh0, bh1, bh2, bh3, wh_base + boff);
        ldmx4t(bh4, bh5, bh6, bh7, wh_base + boff + 32);
        ldmx4t(bl0, bl1, bl2, bl3, wl_base + boff);
        ldmx4t(bl4, bl5, bl6, bl7, wl_base + boff + 32);
        mma16816(acc[0][0], acc[0][1], acc[0][2], acc[0][3], ah0, ah1, ah2, ah3, bh0, bh1);
        mma16816(acc[1][0], acc[1][1], acc[1][2], acc[1][3], ah0, ah1, ah2, ah3, bh2, bh3);
        mma16816(acc[2][0], acc[2][1], acc[2][2], acc[2][3], ah0, ah1, ah2, ah3, bh4, bh5);
        mma16816(acc[3][0], acc[3][1], acc[3][2], acc[3][3], ah0, ah1, ah2, ah3, bh6, bh7);
        mma16816(acc[0][0], acc[0][1], acc[0][2], acc[0][3], ah0, ah1, ah2, ah3, bl0, bl1);
        mma16816(acc[1][0], acc[1][1], acc[1][2], acc[1][3], ah0, ah1, ah2, ah3, bl2, bl3);
        mma16816(acc[2][0], acc[2][1], acc[2][2], acc[2][3], ah0, ah1, ah2, ah3, bl4, bl5);
        mma16816(acc[3][0], acc[3][1], acc[3][2], acc[3][3], ah0, ah1, ah2, ah3, bl6, bl7);
        mma16816(acc[0][0], acc[0][1], acc[0][2], acc[0][3], al0, al1, al2, al3, bh0, bh1);
        mma16816(acc[1][0], acc[1][1], acc[1][2], acc[1][3], al0, al1, al2, al3, bh2, bh3);
        mma16816(acc[2][0], acc[2][1], acc[2][2], acc[2][3], al0, al1, al2, al3, bh4, bh5);
        mma16816(acc[3][0], acc[3][1], acc[3][2], acc[3][3], al0, al1, al2, al3, bh6, bh7);
    }
    __syncthreads();   // all GEMM1 reads of ah/al/wh/wl done

    // ReLU + split write back to ah/al; stash W2 -> wh/wl
    #pragma unroll
    for (int t = 0; t < 4; t++) {
        int c0 = nw * 32 + t * 8 + qc;
        float r0 = fmaxf(acc[t][0], 0.f), r1 = fmaxf(acc[t][1], 0.f);
        float r2 = fmaxf(acc[t][2], 0.f), r3 = fmaxf(acc[t][3], 0.f);
        __half h0, l0, h1, l1;
        split_h(r0, h0, l0); split_h(r1, h1, l1);
        *(__half2*)&ah_[(mw * 16 + row) * 72 + c0] = __halves2half2(h0, h1);
        *(__half2*)&al_[(mw * 16 + row) * 72 + c0] = __halves2half2(l0, l1);
        split_h(r2, h0, l0); split_h(r3, h1, l1);
        *(__half2*)&ah_[(mw * 16 + row + 8) * 72 + c0] = __halves2half2(h0, h1);
        *(__half2*)&al_[(mw * 16 + row + 8) * 72 + c0] = __halves2half2(l0, l1);
    }
    {
        int i0 = tid * 16;
        #pragma unroll
        for (int j = 0; j < 2; j++) {
            int idx = i0 + j * 8;
            int k = idx >> 6, n = idx & 63;
            *(uint4*)&wh_[k * 72 + n] = s2h[j];
            *(uint4*)&wl_[k * 72 + n] = s2l[j];
        }
    }
    __syncthreads();

    // ---- GEMM 2 (3-term split) ----
    #pragma unroll
    for (int t = 0; t < 4; t++) {
        float bx = b2s[nw * 32 + t * 8 + qc];
        float by = b2s[nw * 32 + t * 8 + qc + 1];
        acc[t][0] = bx; acc[t][1] = by; acc[t][2] = bx; acc[t][3] = by;
    }
    #pragma unroll
    for (int k0 = 0; k0 < 64; k0 += 16) {
        uint32_t aoff = (uint32_t)((a_row * 72 + k0 + a_koff) * 2);
        uint32_t boff = (uint32_t)(((k0 + b_krow) * 72 + b_ncol) * 2);
        uint32_t ah0, ah1, ah2, ah3, al0, al1, al2, al3;
        ldmx4(ah0, ah1, ah2, ah3, ah_base + aoff);
        ldmx4(al0, al1, al2, al3, al_base + aoff);
        uint32_t bh0, bh1, bh2, bh3, bh4, bh5, bh6, bh7;
        uint32_t bl0, bl1, bl2, bl3, bl4, bl5, bl6, bl7;
        ldmx4t(bh0, bh1, bh2, bh3, wh_base + boff);
        ldmx4t(bh4, bh5, bh6, bh7, wh_base + boff + 32);
        ldmx4t(bl0, bl1, bl2, bl3, wl_base + boff);
        ldmx4t(bl4, bl5, bl6, bl7, wl_base + boff + 32);
        mma16816(acc[0][0], acc[0][1], acc[0][2], acc[0][3], ah0, ah1, ah2, ah3, bh0, bh1);
        mma16816(acc[1][0], acc[1][1], acc[1][2], acc[1][3], ah0, ah1, ah2, ah3, bh2, bh3);
        mma16816(acc[2][0], acc[2][1], acc[2][2], acc[2][3], ah0, ah1, ah2, ah3, bh4, bh5);
        mma16816(acc[3][0], acc[3][1], acc[3][2], acc[3][3], ah0, ah1, ah2, ah3, bh6, bh7);
        mma16816(acc[0][0], acc[0][1], acc[0][2], acc[0][3], ah0, ah1, ah2, ah3, bl0, bl1);
        mma16816(acc[1][0], acc[1][1], acc[1][2], acc[1][3], ah0, ah1, ah2, ah3, bl2, bl3);
        mma16816(acc[2][0], acc[2][1], acc[2][2], acc[2][3], ah0, ah1, ah2, ah3, bl4, bl5);
        mma16816(acc[3][0], acc[3][1], acc[3][2], acc[3][3], ah0, ah1, ah2, ah3, bl6, bl7);
        mma16816(acc[0][0], acc[0][1], acc[0][2], acc[0][3], al0, al1, al2, al3, bh0, bh1);
        mma16816(acc[1][0], acc[1][1], acc[1][2], acc[1][3], al0, al1, al2, al3, bh2, bh3);
        mma16816(acc[2][0], acc[2][1], acc[2][2], acc[2][3], al0, al1, al2, al3, bh4, bh5);
        mma16816(acc[3][0], acc[3][1], acc[3][2], acc[3][3], al0, al1, al2, al3, bh6, bh7);
    }
    __syncthreads();   // GEMM2 reads of u_area done before o_f overwrite

    // ---- epilogue: fp32 out to gmem + smem tile for stats ----
    {
        int r1 = mw * 16 + row;
        int node1 = n0 + r1;
        #pragma unroll
        for (int t = 0; t < 4; t++) {
            int c0 = nw * 32 + t * 8 + qc;
            o_f[r1 * 65 + c0]           = acc[t][0];
            o_f[r1 * 65 + c0 + 1]       = acc[t][1];
            o_f[(r1 + 8) * 65 + c0]     = acc[t][2];
            o_f[(r1 + 8) * 65 + c0 + 1] = acc[t][3];
            if (node1 < NN)
                *(float2*)&g_bufA[node1 * HH + c0] = make_float2(acc[t][0], acc[t][1]);
            if (node1 + 8 < NN)
                *(float2*)&g_bufA[(node1 + 8) * HH + c0] = make_float2(acc[t][2], acc[t][3]);
        }
    }
    __syncthreads();

    // ---- GraphNorm stats (block reduce per graph -> global atomics) ----
    float* ssum = g_ssum3[lidx];
    float* ssq  = g_ssq3[lidx];
    int lastn = min(n0 + 63, NN - 1);
    int gfirst = batch[n0], glast = batch[lastn];
    int c = tid & 63, sub = tid >> 6;
    for (int g = gfirst; g <= glast; g++) {
        int lo = max(n0, g_gstart[g]);
        int hi = min(min(n0 + 64, NN), g_gstart[g + 1]);
        float s = 0.f, q = 0.f;
        for (int n = lo + sub; n < hi; n += 4) {
            float vv = o_f[(n - n0) * 65 + c];
            s += vv; q += vv * vv;
        }
        rs_[tid] = s; rq_[tid] = q;
        __syncthreads();
        if (tid < 64) {
            float ts2 = rs_[tid] + rs_[tid + 64] + rs_[tid + 128] + rs_[tid + 192];
            float tq2 = rq_[tid] + rq_[tid + 64] + rq_[tid + 128] + rq_[tid + 192];
            atomicAdd(&ssum[g * HH + tid], ts2);
            atomicAdd(&ssq[g * HH + tid], tq2);
        }
        __syncthreads();
    }
}

// ---------------- GraphNorm apply (nprep folded in) + ReLU + residual ----------------
// is_last==0: writes hcur + hsum. is_last==1: skips hcur, adds gate logits.
__global__ void k_apply(const int* __restrict__ batch, int lidx, int accum, int is_last,
                        const float* __restrict__ gnw, const float* __restrict__ gnb,
                        const float* __restrict__ gnms,
                        const float* __restrict__ gw, const float* __restrict__ gb) {
    int i4 = blockIdx.x * blockDim.x + threadIdx.x;
    if (i4 >= NN * (HH / 4)) return;
    int node = i4 >> 4;
    int c0 = (i4 & 15) * 4;
    int g = batch[node];

    // inline nprep: per (g, c0..c0+3) scale/shift
    float cnt = fmaxf((float)(g_gstart[g + 1] - g_gstart[g]), 1.f);
    float rc = 1.f / cnt;
    const float4 ss = *(const float4*)&g_ssum3[lidx][g * HH + c0];
    const float4 sq = *(const float4*)&g_ssq3[lidx][g * HH + c0];
    const float4 wv = *(const float4*)&gnw[c0];
    const float4 bv = *(const float4*)&gnb[c0];
    const float4 mv = *(const float4*)&gnms[c0];
    float4 sc, sh;
    {
        float mean = ss.x * rc, ex2 = sq.x * rc, ms = mv.x;
        float var = ex2 - (2.f * ms - ms * ms) * mean * mean;
        sc.x = rsqrtf(var + GN_EPS) * wv.x;
        sh.x = bv.x - ms * mean * sc.x;
    }
    {
        float mean = ss.y * rc, ex2 = sq.y * rc, ms = mv.y;
        float var = ex2 - (2.f * ms - ms * ms) * mean * mean;
        sc.y = rsqrtf(var + GN_EPS) * wv.y;
        sh.y = bv.y - ms * mean * sc.y;
    }
    {
        float mean = ss.z * rc, ex2 = sq.z * rc, ms = mv.z;
        float var = ex2 - (2.f * ms - ms * ms) * mean * mean;
        sc.z = rsqrtf(var + GN_EPS) * wv.z;
        sh.z = bv.z - ms * mean * sc.z;
    }
    {
        float mean = ss.w * rc, ex2 = sq.w * rc, ms = mv.w;
        float var = ex2 - (2.f * ms - ms * ms) * mean * mean;
        sc.w = rsqrtf(var + GN_EPS) * wv.w;
        sh.w = bv.w - ms * mean * sc.w;
    }

    const float4 v = *(const float4*)&g_bufA[i4 * 4];
    float4 o;
    o.x = fmaxf(v.x * sc.x + sh.x, 0.f);
    o.y = fmaxf(v.y * sc.y + sh.y, 0.f);
    o.z = fmaxf(v.z * sc.z + sh.z, 0.f);
    o.w = fmaxf(v.w * sc.w + sh.w, 0.f);

    float4 hs;
    if (accum) {
        hs = *(const float4*)&g_hsum[i4 * 4];
        hs.x += o.x; hs.y += o.y; hs.z += o.z; hs.w += o.w;
    } else {
        hs = o;
    }
    *(float4*)&g_hsum[i4 * 4] = hs;

    if (!is_last) {
        *(float4*)&g_hcur[i4 * 4] = o;
    } else {
        const float4 w = *(const float4*)&gw[c0];
        float d = hs.x * w.x + hs.y * w.y + hs.z * w.z + hs.w * w.w;
        d += __shfl_down_sync(0xffffffffu, d, 8, 16);
        d += __shfl_down_sync(0xffffffffu, d, 4, 16);
        d += __shfl_down_sync(0xffffffffu, d, 2, 16);
        d += __shfl_down_sync(0xffffffffu, d, 1, 16);
        if ((i4 & 15) == 0) g_gate[node] = d + gb[0];
    }
}

// ---------------- fused pooling + head MLP ----------------
__global__ void k_pool_head(const float* __restrict__ u,
                            const float* __restrict__ hw1, const float* __restrict__ hb1,
                            const float* __restrict__ hw2, const float* __restrict__ hb2,
                            float* __restrict__ out) {
    int b = blockIdx.x;
    int s = g_gstart[b], e = g_gstart[b + 1];
    int tid = threadIdx.x;
    __shared__ float red[256], red2[256], red3[256];
    __shared__ float za[64], zm[64], zx[64], rr[64];
    __shared__ float sM, sD;

    // pass A: max gate
    float m = -INFINITY;
    for (int n = s + tid; n < e; n += 256) m = fmaxf(m, g_gate[n]);
    red[tid] = m;
    __syncthreads();
    for (int o = 128; o > 0; o >>= 1) {
        if (tid < o) red[tid] = fmaxf(red[tid], red[tid + o]);
        __syncthreads();
    }
    if (tid == 0) sM = red[0];
    __syncthreads();
    float mm = sM;

    // pass B: sum exp
    float d = 0.f;
    for (int n = s + tid; n < e; n += 256) d += __expf(g_gate[n] - mm);
    __syncthreads();
    red[tid] = d;
    __syncthreads();
    for (int o = 128; o > 0; o >>= 1) {
        if (tid < o) red[tid] += red[tid + o];
        __syncthreads();
    }
    if (tid == 0) sD = red[0];
    __syncthreads();
    float den = sD;

    // pass C: att / mean / max
    int c = tid & 63, l = tid >> 6;
    float fa = 0.f, fm = 0.f, fx = -INFINITY;
    for (int n = s + l; n < e; n += 4) {
        float hv = g_hsum[n * HH + c];
        float w = __expf(g_gate[n] - mm);
        fa += w * hv; fm += hv; fx = fmaxf(fx, hv);
    }
    __syncthreads();
    red[tid] = fa; red2[tid] = fm; red3[tid] = fx;
    __syncthreads();
    if (tid < 64) {
        float ta = red[tid] + red[tid + 64] + red[tid + 128] + red[tid + 192];
        float tm = red2[tid] + red2[tid + 64] + red2[tid + 128] + red2[tid + 192];
        float tx = fmaxf(fmaxf(red3[tid], red3[tid + 64]), fmaxf(red3[tid + 128], red3[tid + 192]));
        float cnt = fmaxf((float)(e - s), 1.f);
        za[tid] = (e > s) ? (ta / den) : 0.f;
        zm[tid] = tm / cnt;
        zx[tid] = tx;
    }
    __syncthreads();

    if (tid < 64) {
        float a = hb1[tid];
        #pragma unroll 4
        for (int k = 0; k < HH; k++) a += za[k] * hw1[k * HH + tid];
        #pragma unroll 4
        for (int k = 0; k < HH; k++) a += zm[k] * hw1[(HH + k) * HH + tid];
        #pragma unroll 4
        for (int k = 0; k < HH; k++) a += zx[k] * hw1[(2 * HH + k) * HH + tid];
        #pragma unroll
        for (int k = 0; k < 3; k++) a += u[b * 3 + k] * hw1[(3 * HH + k) * HH + tid];
        rr[tid] = fmaxf(a, 0.f) * hw2[tid];
    }
    __syncthreads();
    if (tid == 0) {
        float t = 0.f;
        for (int k = 0; k < 64; k++) t += rr[k];
        out[b] = t + hb2[0];
    }
}

// ---------------- launch ----------------
extern "C" void kernel_launch(void* const* d_in, const int* in_sizes, int n_in,
                              void* d_out, int out_size) {
    const float* x = (const float*)d_in[0];
    const int* ei = (const int*)d_in[1];
    const int* batch = (const int*)d_in[2];
    const float* u = (const float*)d_in[3];
    const float *wA[3], *bA[3], *wB[3], *bB[3], *gnw[3], *gnb[3], *gnms[3];
    int p = 4;
    for (int l = 0; l < 3; l++) {
        wA[l] = (const float*)d_in[p++]; bA[l] = (const float*)d_in[p++];
        wB[l] = (const float*)d_in[p++]; bB[l] = (const float*)d_in[p++];
        gnw[l] = (const float*)d_in[p++]; gnb[l] = (const float*)d_in[p++];
        gnms[l] = (const float*)d_in[p++];
    }
    const float* gate_w = (const float*)d_in[p++];
    const float* gate_b = (const float*)d_in[p++];
    const float* hw1 = (const float*)d_in[p++];
    const float* hb1 = (const float*)d_in[p++];
    const float* hw2 = (const float*)d_in[p++];
    const float* hb2 = (const float*)d_in[p++];
    float* out = (float*)d_out;

    // init (zero + weight pre-split) + CSR build
    k_init<<<(NN + 255) / 256, 256>>>(wA[0], wA[1], wA[2], wB[0], wB[1], wB[2]);
    k_hist<<<(EE + 255) / 256, 256>>>(ei);
    k_scan1<<<SCAN_NBLK, 1024>>>();
    k_scan3<<<(NN + 255) / 256, 256>>>(batch);
    k_fill<<<(EE + 255) / 256, 256>>>(ei);

    // trunk: 3x (fused agg + split-fp16 HMMA MLP + stats -> fused nprep+apply)
    for (int l = 0; l < 3; l++) {
        k_layer<<<(NN + 63) / 64, 256>>>(x, l == 0 ? 1 : 0, l, bA[l], bB[l], batch);
        k_apply<<<(NN * 16 + 255) / 256, 256>>>(batch, l, l == 0 ? 0 : 1, l == 2 ? 1 : 0,
                                                gnw[l], gnb[l], gnms[l], gate_w, gate_b);
    }

    // fused pooling + head
    k_pool_head<<<BB, 256>>>(u, hw1, hb1, hw2, hb2, out);
    (void)in_sizes; (void)n_in; (void)out_size;
}